// round 12
// baseline (speedup 1.0000x reference)
#include <cuda_runtime.h>
#include <cuda_bf16.h>
#include <stdint.h>

#define NEG (-1e9f)
constexpr int B_   = 128;
constexpr int NPG  = 1024;
constexpr int M_   = 24;
constexpr int MAXC = 512;
constexpr int G_   = 8;
constexpr int ND_  = 7;
constexpr int AT_  = 5;
constexpr int P_   = 28;

__device__ int      d_cube_node[B_ * MAXC];
__device__ int      d_group_node[B_ * G_];
__device__ float    d_cm_gc[B_ * 128];
__device__ uint32_t d_W1bf[128 * 68];   // bf16x2 W1^T image, PAIRED u64 layout, stride 68 u32
__device__ uint32_t d_W2bf[24 * 68];    // bf16x2 W2^T image, PAIRED u64 layout

__constant__ int c_IU[P_] = {0,0,0,0,0,0,0,1,1,1,1,1,1,2,2,2,2,2,3,3,3,3,4,4,4,5,5,6};
__constant__ int c_JU[P_] = {1,2,3,4,5,6,7,2,3,4,5,6,7,3,4,5,6,7,4,5,6,7,5,6,7,6,7,7};

__device__ __forceinline__ int mask_mode(const int* __restrict__ atm) {
    int v = __ldg(atm);
    if (v == 1) return 1;
    if (v == 0x3F800000) return 2;
    return 0;
}
__device__ __forceinline__ bool read_mask(const void* p, long i, int mode) {
    if (mode == 1) return ((const int*)p)[i] != 0;
    if (mode == 2) return ((const float*)p)[i] != 0.f;
    return ((const uint8_t*)p)[i] != 0;
}

// bf16 mma.sync (sm_80+ baseline PTX -> HMMA on sm_103)
__device__ __forceinline__ void mma16816(float* c, uint32_t a0, uint32_t a1,
                                         uint32_t a2, uint32_t a3,
                                         uint32_t b0, uint32_t b1) {
    asm volatile(
        "mma.sync.aligned.m16n8k16.row.col.f32.bf16.bf16.f32 "
        "{%0,%1,%2,%3}, {%4,%5,%6,%7}, {%8,%9}, {%0,%1,%2,%3};"
        : "+f"(c[0]), "+f"(c[1]), "+f"(c[2]), "+f"(c[3])
        : "r"(a0), "r"(a1), "r"(a2), "r"(a3), "r"(b0), "r"(b1));
}
__device__ __forceinline__ uint32_t bf2(float x, float y) {
    __nv_bfloat162 p = __float22bfloat162_rn(make_float2(x, y));
    return *(uint32_t*)&p;
}
// paired layout: k-pair kp and kp+4 (same 8-group) share one u64 slot.
// u32 index within a 68-u32 row for k-pair kp (0..63):
__device__ __forceinline__ int pidx(int kp) {
    return 2 * (((kp >> 3) << 2) + (kp & 3)) + ((kp >> 2) & 1);
}
__device__ __forceinline__ uint32_t u64lo(uint64_t v) { return (uint32_t)v; }
__device__ __forceinline__ uint32_t u64hi(uint64_t v) { return (uint32_t)(v >> 32); }

// ---------------------------------------------------------------------------
// setup: blocks 0..127 per-batch work; block 128 converts cube weights to bf16
// ---------------------------------------------------------------------------
__global__ __launch_bounds__(256) void setup_kernel(
    const float* __restrict__ gf,
    const float* __restrict__ cmW1, const float* __restrict__ cmb1,
    const float* __restrict__ cmW2,
    const void* __restrict__ cube_mask, const void* __restrict__ group_mask,
    const int* __restrict__ atm)
{
    const int t = threadIdx.x;
    if (blockIdx.x == B_) {
        const int n = t & 127, kh = (t >> 7) * 32;
        const float* wp = cmW1 + n;
        #pragma unroll 8
        for (int kk = 0; kk < 32; kk++) {
            int kp = kh + kk;
            float w0 = __ldg(wp + (2 * kp) * 128);
            float w1 = __ldg(wp + (2 * kp + 1) * 128);
            d_W1bf[n * 68 + pidx(kp)] = bf2(w0, w1);
        }
        for (int idx = t; idx < 24 * 64; idx += 256) {
            int nn = idx % 24, kp = idx / 24;
            float w0 = __ldg(cmW2 + (2 * kp) * 24 + nn);
            float w1 = __ldg(cmW2 + (2 * kp + 1) * 24 + nn);
            d_W2bf[nn * 68 + pidx(kp)] = bf2(w0, w1);
        }
        return;
    }

    const int b = blockIdx.x;
    const int w = t >> 5, lane = t & 31;
    const int mode = mask_mode(atm);
    __shared__ float g[128];
    __shared__ float sred[4][128];
    __shared__ int wtc[4], wtg[4], stc, stg;

    if (t < 128) g[t] = gf[b * 128 + t];
    __syncthreads();

    unsigned cm8 = 0, gm8 = 0;
    int cex = 0, gex = 0;

    if (w < 4) {
        const float4* W4 = (const float4*)cmW1;
        float4 a = make_float4(0.f, 0.f, 0.f, 0.f);
        #pragma unroll
        for (int kk = 0; kk < 32; kk++) {
            int k = 32 * w + kk;
            float4 wv = __ldg(&W4[(128 + k) * 32 + lane]);
            float gk = g[k];
            a.x = fmaf(gk, wv.x, a.x);
            a.y = fmaf(gk, wv.y, a.y);
            a.z = fmaf(gk, wv.z, a.z);
            a.w = fmaf(gk, wv.w, a.w);
        }
        *(float4*)&sred[w][4 * lane] = a;
    } else if (mode == 1) {
        const int w4 = w - 4;
        const int4* cm4 = (const int4*)cube_mask + b * 256 + w4 * 64 + lane * 2;
        const int4* gm4 = (const int4*)group_mask + b * 256 + w4 * 64 + lane * 2;
        int4 c0 = __ldg(cm4), c1 = __ldg(cm4 + 1);
        int4 g0 = __ldg(gm4), g1 = __ldg(gm4 + 1);
        cm8 = (c0.x != 0) | ((c0.y != 0) << 1) | ((c0.z != 0) << 2) | ((c0.w != 0) << 3)
            | ((c1.x != 0) << 4) | ((c1.y != 0) << 5) | ((c1.z != 0) << 6) | ((c1.w != 0) << 7);
        gm8 = (g0.x != 0) | ((g0.y != 0) << 1) | ((g0.z != 0) << 2) | ((g0.w != 0) << 3)
            | ((g1.x != 0) << 4) | ((g1.y != 0) << 5) | ((g1.z != 0) << 6) | ((g1.w != 0) << 7);
        int cs = __popc(cm8), gs = __popc(gm8);
        int csi = cs, gsi = gs;
        #pragma unroll
        for (int off = 1; off < 32; off <<= 1) {
            int v1 = __shfl_up_sync(0xffffffffu, csi, off);
            int v2 = __shfl_up_sync(0xffffffffu, gsi, off);
            if (lane >= off) { csi += v1; gsi += v2; }
        }
        cex = csi - cs; gex = gsi - gs;
        if (lane == 31) { wtc[w4] = csi; wtg[w4] = gsi; }
    } else if (w == 4) {
        int cc = 0, gc = 0;
        for (int c = 0; c < NPG; c += 32) {
            long node = (long)b * NPG + c + lane;
            bool cm = read_mask(cube_mask, node, mode);
            bool gm = read_mask(group_mask, node, mode);
            unsigned cb = __ballot_sync(0xffffffffu, cm);
            unsigned gb = __ballot_sync(0xffffffffu, gm);
            unsigned lt = (1u << lane) - 1u;
            if (cm) { int p = cc + __popc(cb & lt); if (p < MAXC) d_cube_node[b * MAXC + p] = (int)node; }
            if (gm) { int p = gc + __popc(gb & lt); if (p < G_)   d_group_node[b * G_ + p] = (int)node; }
            cc += __popc(cb);
            gc += __popc(gb);
        }
        if (lane == 0) { stc = cc; stg = gc; }
    }
    __syncthreads();

    if (t < 128)
        d_cm_gc[b * 128 + t] = __ldg(cmb1 + t) +
            ((sred[0][t] + sred[1][t]) + (sred[2][t] + sred[3][t]));

    int tc, tg;
    if (mode == 1) {
        tc = wtc[0] + wtc[1] + wtc[2] + wtc[3];
        tg = wtg[0] + wtg[1] + wtg[2] + wtg[3];
        if (w >= 4) {
            const int w4 = w - 4;
            int cbase = 0, gbase = 0;
            #pragma unroll
            for (int i = 0; i < 4; i++) if (i < w4) { cbase += wtc[i]; gbase += wtg[i]; }
            const int nb = b * NPG + w4 * 256 + lane * 8;
            #pragma unroll
            for (int j = 0; j < 8; j++) {
                if ((cm8 >> j) & 1) {
                    int p = cbase + cex + __popc(cm8 & ((1u << j) - 1u));
                    if (p < MAXC) d_cube_node[b * MAXC + p] = nb + j;
                }
                if ((gm8 >> j) & 1) {
                    int p = gbase + gex + __popc(gm8 & ((1u << j) - 1u));
                    if (p < G_) d_group_node[b * G_ + p] = nb + j;
                }
            }
        }
    } else {
        tc = stc; tg = stg;
    }
    for (int p = tc + t; p < MAXC; p += 256) d_cube_node[b * MAXC + p] = -1;
    for (int p = tg + t; p < G_; p += 256)   d_group_node[b * G_ + p] = -1;
}

// ---------------------------------------------------------------------------
// mega kernel, 256 threads/block, 3 blocks/SM:
//   blocks 0-511 cube (mma.sync bf16, paired-u64 LDS), 512-639 dock, 640-767 man+AT
// cube dyn smem: Xs 0..34816 | Ws1 ..69632 | Ws2 ..76160 | nodes ..76672
// ---------------------------------------------------------------------------
constexpr int SMEM_DYN = 76672;

__global__ __launch_bounds__(256, 3) void mega_kernel(
    const float* __restrict__ nodef, const float* __restrict__ gf,
    const int* __restrict__ atm, const void* __restrict__ move_mask,
    const void* __restrict__ dvm, const void* __restrict__ mvm,
    const float* __restrict__ cm_b2,
    const float* __restrict__ at_W1, const float* __restrict__ at_b1,
    const float* __restrict__ at_W2, const float* __restrict__ at_b2,
    const float* __restrict__ dk_W1, const float* __restrict__ dk_b1,
    const float* __restrict__ dk_W2, const float* __restrict__ dk_b2,
    const float* __restrict__ dk_W3, const float* __restrict__ dk_b3,
    const float* __restrict__ mn_W1, const float* __restrict__ mn_b1,
    const float* __restrict__ mn_W2, const float* __restrict__ mn_b2,
    float* __restrict__ out_at, float* __restrict__ out_cube,
    float* __restrict__ out_dock, float* __restrict__ out_man)
{
    extern __shared__ __align__(16) char smem_raw[];
    const int t = threadIdx.x;
    const int mode = mask_mode(atm);

    if (blockIdx.x < 512) {
        // ===================== CUBE =====================
        uint32_t* Xs  = (uint32_t*)smem_raw;                 // [128][68] paired
        uint32_t* Ws1 = (uint32_t*)(smem_raw + 34816);       // paired
        uint32_t* Ws2 = (uint32_t*)(smem_raw + 69632);       // paired
        int*   nodes = (int*)(smem_raw + 76160);

        const int row0 = blockIdx.x * 128;
        const int b = row0 >> 9;
        const int w = t >> 5, lane = t & 31;
        const int gid4 = lane >> 2, tig = lane & 3;

        // W images: coalesced uint4 copies from precomputed globals (L2-hot)
        {
            const uint4* src1 = (const uint4*)d_W1bf;
            uint4* dst1 = (uint4*)Ws1;
            #pragma unroll
            for (int i = 0; i < 8; i++) dst1[t + i * 256] = src1[t + i * 256];
            if (t < 128) dst1[t + 2048] = src1[t + 2048];
            const uint4* src2 = (const uint4*)d_W2bf;
            uint4* dst2 = (uint4*)Ws2;
            if (t < 204) { dst2[t] = src2[t]; dst2[t + 204] = src2[t + 204]; }
        }
        if (t < 128) nodes[t] = d_cube_node[row0 + t];
        // X: warp-per-row, paired-layout scatter (2 STS.32 per float4)
        #pragma unroll
        for (int i = 0; i < 16; i++) {
            int r = 16 * w + i;
            int nd = __ldg(&d_cube_node[row0 + r]);
            uint32_t v0 = 0u, v1 = 0u;
            if (nd >= 0) {
                float4 x = __ldg((const float4*)(nodef + (size_t)nd * 128) + lane);
                v0 = bf2(x.x, x.y);
                v1 = bf2(x.z, x.w);
            }
            Xs[r * 68 + pidx(2 * lane)]     = v0;
            Xs[r * 68 + pidx(2 * lane + 1)] = v1;
        }
        __syncthreads();

        const int ar0 = 16 * w + gid4;
        const uint64_t* XP0 = (const uint64_t*)Xs + ar0 * 34 + tig;
        const uint64_t* XP1 = (const uint64_t*)Xs + (ar0 + 8) * 34 + tig;
        const uint64_t* WP1 = (const uint64_t*)Ws1;
        const uint64_t* WP2 = (const uint64_t*)Ws2;
        const float* gcp = d_cm_gc + b * 128;

        float acc[8][4];
        uint32_t h0[16];

        // ---- GEMM1 pass 0: out cols 0..63 ----
        #pragma unroll
        for (int i = 0; i < 8; i++)
            #pragma unroll
            for (int j = 0; j < 4; j++) acc[i][j] = 0.f;
        #pragma unroll
        for (int ks = 0; ks < 8; ks++) {
            uint64_t A0 = XP0[ks * 4], A1 = XP1[ks * 4];
            #pragma unroll
            for (int nt = 0; nt < 8; nt++) {
                uint64_t Bv = WP1[(8 * nt + gid4) * 34 + ks * 4 + tig];
                mma16816(acc[nt], u64lo(A0), u64lo(A1), u64hi(A0), u64hi(A1),
                         u64lo(Bv), u64hi(Bv));
            }
        }
        #pragma unroll
        for (int nt = 0; nt < 8; nt++) {
            int c0 = 8 * nt + 2 * tig;
            float g0 = __ldg(gcp + c0), g1 = __ldg(gcp + c0 + 1);
            h0[nt]     = bf2(fmaxf(acc[nt][0] + g0, 0.f), fmaxf(acc[nt][1] + g1, 0.f));
            h0[nt + 8] = bf2(fmaxf(acc[nt][2] + g0, 0.f), fmaxf(acc[nt][3] + g1, 0.f));
        }

        // ---- GEMM1 pass 1: out cols 64..127 ----
        #pragma unroll
        for (int i = 0; i < 8; i++)
            #pragma unroll
            for (int j = 0; j < 4; j++) acc[i][j] = 0.f;
        #pragma unroll
        for (int ks = 0; ks < 8; ks++) {
            uint64_t A0 = XP0[ks * 4], A1 = XP1[ks * 4];
            #pragma unroll
            for (int nt = 0; nt < 8; nt++) {
                uint64_t Bv = WP1[(64 + 8 * nt + gid4) * 34 + ks * 4 + tig];
                mma16816(acc[nt], u64lo(A0), u64lo(A1), u64hi(A0), u64hi(A1),
                         u64lo(Bv), u64hi(Bv));
            }
        }
        // write H (both halves) over A rows in paired layout (all A reads complete)
        #pragma unroll
        for (int nt = 0; nt < 8; nt++) {
            int kpl = 4 * nt + tig;         // pass0 k-pair
            int kph = 32 + 4 * nt + tig;    // pass1 k-pair
            int c1 = 64 + 8 * nt + 2 * tig;
            float g0 = __ldg(gcp + c1), g1 = __ldg(gcp + c1 + 1);
            Xs[ar0 * 68 + pidx(kpl)]       = h0[nt];
            Xs[(ar0 + 8) * 68 + pidx(kpl)] = h0[nt + 8];
            Xs[ar0 * 68 + pidx(kph)]       = bf2(fmaxf(acc[nt][0] + g0, 0.f), fmaxf(acc[nt][1] + g1, 0.f));
            Xs[(ar0 + 8) * 68 + pidx(kph)] = bf2(fmaxf(acc[nt][2] + g0, 0.f), fmaxf(acc[nt][3] + g1, 0.f));
        }
        __syncwarp();

        // GEMM2: H @ W2^T (N=24)
        float acc2[3][4];
        #pragma unroll
        for (int i = 0; i < 3; i++)
            #pragma unroll
            for (int j = 0; j < 4; j++) acc2[i][j] = 0.f;
        #pragma unroll
        for (int ks = 0; ks < 8; ks++) {
            uint64_t A0 = XP0[ks * 4], A1 = XP1[ks * 4];
            #pragma unroll
            for (int nt = 0; nt < 3; nt++) {
                uint64_t Bv = WP2[(8 * nt + gid4) * 34 + ks * 4 + tig];
                mma16816(acc2[nt], u64lo(A0), u64lo(A1), u64hi(A0), u64hi(A1),
                         u64lo(Bv), u64hi(Bv));
            }
        }
        __syncwarp();   // warp's Xs reads done before overwrite as D-stage

        // stage D2+bias into warp-own region of Xs (384 floats)
        float* Dw = (float*)(Xs + (16 * w) * 68);
        #pragma unroll
        for (int nt = 0; nt < 3; nt++) {
            int c0 = 8 * nt + 2 * tig;
            float bb0 = __ldg(cm_b2 + c0), bb1 = __ldg(cm_b2 + c0 + 1);
            Dw[gid4 * 24 + c0]           = acc2[nt][0] + bb0;
            Dw[gid4 * 24 + c0 + 1]       = acc2[nt][1] + bb1;
            Dw[(gid4 + 8) * 24 + c0]     = acc2[nt][2] + bb0;
            Dw[(gid4 + 8) * 24 + c0 + 1] = acc2[nt][3] + bb1;
        }
        __syncwarp();

        // warp-local masked vector write: 96 float4
        const long e0 = (long)(row0 + 16 * w) * 24;
        #pragma unroll
        for (int j = 0; j < 3; j++) {
            int idx4 = j * 32 + lane;
            float4 v = ((const float4*)Dw)[idx4];
            float r4[4] = {v.x, v.y, v.z, v.w};
            float o4[4];
            if (mode == 1) {
                int4 mk = __ldg((const int4*)move_mask + (e0 >> 2) + idx4);
                int m4[4] = {mk.x, mk.y, mk.z, mk.w};
                #pragma unroll
                for (int q = 0; q < 4; q++) {
                    int e = idx4 * 4 + q;
                    bool ok = (nodes[16 * w + e / 24] >= 0) && (m4[q] != 0);
                    o4[q] = ok ? r4[q] : NEG;
                }
            } else {
                #pragma unroll
                for (int q = 0; q < 4; q++) {
                    int e = idx4 * 4 + q;
                    bool ok = (nodes[16 * w + e / 24] >= 0) && read_mask(move_mask, e0 + e, mode);
                    o4[q] = ok ? r4[q] : NEG;
                }
            }
            *(float4*)(out_cube + e0 + idx4 * 4) = make_float4(o4[0], o4[1], o4[2], o4[3]);
        }
        return;
    }

    // ===================== HEADS =====================
    const int hb = blockIdx.x - 512;
    const int b = hb & 127;
    if (hb < 128) {
        // ---------- DOCKING ----------
        float* gf8 = (float*)smem_raw;
        float* gl  = (float*)(smem_raw + 4096);
        float* uu  = (float*)(smem_raw + 4608);
        float* vv  = (float*)(smem_raw + 8704);
        float* ww  = (float*)(smem_raw + 12800);
        float* W3s = (float*)(smem_raw + 13312);
        int*   gid = (int*)  (smem_raw + 13568);
        float* W2s = (float*)(smem_raw + 13600);

        if (t < G_) gid[t] = d_group_node[b * G_ + t];
        if (t >= 128) gl[t - 128] = gf[b * 128 + (t - 128)];
        __syncthreads();
        #pragma unroll
        for (int i = 0; i < 4; i++) {
            int idx = t + i * 256;
            int g = idx >> 7, c = idx & 127;
            int n = gid[g];
            gf8[g * 128 + c] = (n >= 0) ? __ldg(nodef + (size_t)n * 128 + c) : 0.f;
        }
        #pragma unroll
        for (int i = 0; i < 32; i++) W2s[t + i * 256] = __ldg(dk_W2 + t + i * 256);
        if (t < 64) W3s[t] = __ldg(dk_W3 + t);
        __syncthreads();

        if (t < 128) {
            float ua[G_], va[G_];
            #pragma unroll
            for (int g = 0; g < G_; g++) { ua[g] = 0.f; va[g] = 0.f; }
            float wv = __ldg(dk_b1 + t);
            #pragma unroll 4
            for (int k = 0; k < 128; k++) {
                float wa = __ldg(dk_W1 + k * 128 + t);
                float wb = __ldg(dk_W1 + (128 + k) * 128 + t);
                float wc = __ldg(dk_W1 + (256 + k) * 128 + t);
                #pragma unroll
                for (int g = 0; g < G_; g++) {
                    float x = gf8[g * 128 + k];
                    ua[g] = fmaf(x, wa, ua[g]);
                    va[g] = fmaf(x, wb, va[g]);
                }
                wv = fmaf(gl[k], wc, wv);
            }
            #pragma unroll
            for (int g = 0; g < G_; g++) { uu[g * 128 + t] = ua[g]; vv[g * 128 + t] = va[g]; }
            ww[t] = wv;
        }
        __syncthreads();

        const int wp = t >> 5, lane = t & 31;
        const float b2a = __ldg(dk_b2 + lane);
        const float b2b = __ldg(dk_b2 + lane + 32);
        const float b3v = __ldg(dk_b3);
        const float w3a = W3s[lane], w3b = W3s[lane + 32];

        #pragma unroll
        for (int jj = 0; jj < 2; jj++) {
            const int p0 = wp + 16 * jj;
            const int p1r = p0 + 8;
            const bool has1 = p1r < P_;
            const int p1 = has1 ? p1r : p0;
            const int i0 = c_IU[p0], j0 = c_JU[p0];
            const int i1 = c_IU[p1], j1 = c_JU[p1];
            float s0a = 0.f, s0b = 0.f, s1a = 0.f, s1b = 0.f;
            #pragma unroll 4
            for (int k = 0; k < 128; k++) {
                float wk = ww[k];
                float h0 = fmaxf(uu[i0 * 128 + k] + vv[j0 * 128 + k] + wk, 0.f);
                float h1 = fmaxf(uu[i1 * 128 + k] + vv[j1 * 128 + k] + wk, 0.f);
                float w2a = W2s[k * 64 + lane];
                float w2b = W2s[k * 64 + lane + 32];
                s0a = fmaf(h0, w2a, s0a);
                s0b = fmaf(h0, w2b, s0b);
                s1a = fmaf(h1, w2a, s1a);
                s1b = fmaf(h1, w2b, s1b);
            }
            float c0 = fmaxf(s0a + b2a, 0.f) * w3a + fmaxf(s0b + b2b, 0.f) * w3b;
            float c1 = fmaxf(s1a + b2a, 0.f) * w3a + fmaxf(s1b + b2b, 0.f) * w3b;
            #pragma unroll
            for (int off = 16; off; off >>= 1) {
                c0 += __shfl_down_sync(0xffffffffu, c0, off);
                c1 += __shfl_down_sync(0xffffffffu, c1, off);
            }
            if (lane == 0) {
                bool ok0 = read_mask(dvm, b * P_ + p0, mode) && gid[i0] >= 0 && gid[j0] >= 0;
                out_dock[b * P_ + p0] = ok0 ? (c0 + b3v) : NEG;
                if (has1) {
                    bool ok1 = read_mask(dvm, b * P_ + p1, mode) && gid[i1] >= 0 && gid[j1] >= 0;
                    out_dock[b * P_ + p1] = ok1 ? (c1 + b3v) : NEG;
                }
            }
        }
    } else {
        // ---------- MANEUVER + ACTION TYPE ----------
        float* gf8  = (float*)smem_raw;
        float* gl   = (float*)(smem_raw + 4096);
        float* manH = (float*)(smem_raw + 4608);
        float* ath  = (float*)(smem_raw + 8704);
        float* W2m  = (float*)(smem_raw + 8960);
        int*   gid  = (int*)  (smem_raw + 12544);

        if (t < G_) gid[t] = d_group_node[b * G_ + t];
        if (t >= 128) gl[t - 128] = gf[b * 128 + (t - 128)];
        __syncthreads();
        #pragma unroll
        for (int i = 0; i < 4; i++) {
            int idx = t + i * 256;
            int g = idx >> 7, c = idx & 127;
            int n = gid[g];
            gf8[g * 128 + c] = (n >= 0) ? __ldg(nodef + (size_t)n * 128 + c) : 0.f;
        }
        for (int idx = t; idx < 128 * ND_; idx += 256) W2m[idx] = __ldg(mn_W2 + idx);
        __syncthreads();

        if (t < 128) {
            float ma[G_];
            #pragma unroll
            for (int g = 0; g < G_; g++) ma[g] = 0.f;
            float gcm = __ldg(mn_b1 + t);
            float av = (t < 64) ? __ldg(at_b1 + t) : 0.f;
            #pragma unroll 4
            for (int k = 0; k < 128; k++) {
                float wa = __ldg(mn_W1 + k * 128 + t);
                float wb = __ldg(mn_W1 + (128 + k) * 128 + t);
                float gk = gl[k];
                #pragma unroll
                for (int g = 0; g < G_; g++) ma[g] = fmaf(gf8[g * 128 + k], wa, ma[g]);
                gcm = fmaf(gk, wb, gcm);
                if (t < 64) av = fmaf(gk, __ldg(at_W1 + k * 64 + t), av);
            }
            #pragma unroll
            for (int g = 0; g < G_; g++) manH[g * 128 + t] = fmaxf(ma[g] + gcm, 0.f);
            if (t < 64) ath[t] = fmaxf(av, 0.f);
        }
        __syncthreads();

        if (t < G_ * ND_) {
            int g = t / ND_, d = t - g * ND_;
            float s = __ldg(mn_b2 + d);
            #pragma unroll 8
            for (int k = 0; k < 128; k++) s = fmaf(manH[g * 128 + k], W2m[k * ND_ + d], s);
            bool ok = (gid[g] >= 0) && read_mask(mvm, b * G_ * ND_ + t, mode);
            out_man[b * G_ * ND_ + t] = ok ? s : NEG;
        } else if (t >= 64 && t < 64 + AT_) {
            int a = t - 64;
            float s = __ldg(at_b2 + a);
            #pragma unroll 8
            for (int k = 0; k < 64; k++) s = fmaf(ath[k], __ldg(at_W2 + k * AT_ + a), s);
            out_at[b * AT_ + a] = read_mask(atm, b * AT_ + a, mode) ? s : NEG;
        }
    }
}

// ---------------------------------------------------------------------------
extern "C" void kernel_launch(void* const* d_in, const int* in_sizes, int n_in,
                              void* d_out, int out_size) {
    const float* nodef      = (const float*)d_in[0];
    const float* gf         = (const float*)d_in[1];
    const int*   atm        = (const int*)d_in[2];
    const void*  cube_mask  = d_in[3];
    const void*  group_mask = d_in[4];
    /* d_in[5] = batch (unused; segments contiguous) */
    const void*  move_mask  = d_in[6];
    const void*  dvm        = d_in[7];
    const void*  mvm        = d_in[8];
    const float* at_W1 = (const float*)d_in[9];
    const float* at_b1 = (const float*)d_in[10];
    const float* at_W2 = (const float*)d_in[11];
    const float* at_b2 = (const float*)d_in[12];
    const float* cm_W1 = (const float*)d_in[13];
    const float* cm_b1 = (const float*)d_in[14];
    const float* cm_W2 = (const float*)d_in[15];
    const float* cm_b2 = (const float*)d_in[16];
    const float* dk_W1 = (const float*)d_in[17];
    const float* dk_b1 = (const float*)d_in[18];
    const float* dk_W2 = (const float*)d_in[19];
    const float* dk_b2 = (const float*)d_in[20];
    const float* dk_W3 = (const float*)d_in[21];
    const float* dk_b3 = (const float*)d_in[22];
    const float* mn_W1 = (const float*)d_in[23];
    const float* mn_b1 = (const float*)d_in[24];
    const float* mn_W2 = (const float*)d_in[25];
    const float* mn_b2 = (const float*)d_in[26];

    float* out      = (float*)d_out;
    float* out_at   = out;
    float* out_cube = out + (size_t)B_ * AT_;
    float* out_dock = out_cube + (size_t)B_ * MAXC * M_;
    float* out_man  = out_dock + (size_t)B_ * P_;

    cudaFuncSetAttribute(mega_kernel, cudaFuncAttributeMaxDynamicSharedMemorySize, SMEM_DYN);

    setup_kernel<<<B_ + 1, 256>>>(gf, cm_W1, cm_b1, cm_W2, cube_mask, group_mask, atm);
    mega_kernel<<<768, 256, SMEM_DYN>>>(
        nodef, gf, atm, move_mask, dvm, mvm,
        cm_b2,
        at_W1, at_b1, at_W2, at_b2,
        dk_W1, dk_b1, dk_W2, dk_b2, dk_W3, dk_b3,
        mn_W1, mn_b1, mn_W2, mn_b2,
        out_at, out_cube, out_dock, out_man);
}

// round 13
// speedup vs baseline: 1.0853x; 1.0853x over previous
#include <cuda_runtime.h>
#include <cuda_bf16.h>
#include <stdint.h>

#define NEG (-1e9f)
constexpr int B_   = 128;
constexpr int NPG  = 1024;
constexpr int M_   = 24;
constexpr int MAXC = 512;
constexpr int G_   = 8;
constexpr int ND_  = 7;
constexpr int AT_  = 5;
constexpr int P_   = 28;

__device__ int      d_cube_node[B_ * MAXC];
__device__ int      d_group_node[B_ * G_];
__device__ float    d_cm_gc[B_ * 128];
__device__ uint32_t d_W1bf[128 * 68];   // bf16x2 W1^T image (n-major, stride 68 u32)
__device__ uint32_t d_W2bf[24 * 68];    // bf16x2 W2^T image

__constant__ int c_IU[P_] = {0,0,0,0,0,0,0,1,1,1,1,1,1,2,2,2,2,2,3,3,3,3,4,4,4,5,5,6};
__constant__ int c_JU[P_] = {1,2,3,4,5,6,7,2,3,4,5,6,7,3,4,5,6,7,4,5,6,7,5,6,7,6,7,7};

__device__ __forceinline__ int mask_mode(const int* __restrict__ atm) {
    int v = __ldg(atm);
    if (v == 1) return 1;
    if (v == 0x3F800000) return 2;
    return 0;
}
__device__ __forceinline__ bool read_mask(const void* p, long i, int mode) {
    if (mode == 1) return ((const int*)p)[i] != 0;
    if (mode == 2) return ((const float*)p)[i] != 0.f;
    return ((const uint8_t*)p)[i] != 0;
}

// bf16 mma.sync (sm_80+ baseline PTX -> HMMA on sm_103)
__device__ __forceinline__ void mma16816(float* c, uint32_t a0, uint32_t a1,
                                         uint32_t a2, uint32_t a3,
                                         uint32_t b0, uint32_t b1) {
    asm volatile(
        "mma.sync.aligned.m16n8k16.row.col.f32.bf16.bf16.f32 "
        "{%0,%1,%2,%3}, {%4,%5,%6,%7}, {%8,%9}, {%0,%1,%2,%3};"
        : "+f"(c[0]), "+f"(c[1]), "+f"(c[2]), "+f"(c[3])
        : "r"(a0), "r"(a1), "r"(a2), "r"(a3), "r"(b0), "r"(b1));
}
__device__ __forceinline__ void ldsm4(uint32_t& r0, uint32_t& r1, uint32_t& r2,
                                      uint32_t& r3, uint32_t addr) {
    asm volatile("ldmatrix.sync.aligned.m8n8.x4.shared.b16 {%0,%1,%2,%3}, [%4];"
                 : "=r"(r0), "=r"(r1), "=r"(r2), "=r"(r3) : "r"(addr));
}
__device__ __forceinline__ void ldsm2(uint32_t& r0, uint32_t& r1, uint32_t addr) {
    asm volatile("ldmatrix.sync.aligned.m8n8.x2.shared.b16 {%0,%1}, [%2];"
                 : "=r"(r0), "=r"(r1) : "r"(addr));
}
__device__ __forceinline__ uint32_t smem_u32(const void* p) {
    uint32_t a;
    asm("{ .reg .u64 tmp; cvta.to.shared.u64 tmp, %1; cvt.u32.u64 %0, tmp; }"
        : "=r"(a) : "l"(p));
    return a;
}
__device__ __forceinline__ uint32_t bf2(float x, float y) {
    __nv_bfloat162 p = __float22bfloat162_rn(make_float2(x, y));
    return *(uint32_t*)&p;
}

// ---------------------------------------------------------------------------
// setup: blocks 0..127 per-batch work; block 128 converts cube weights to bf16
// ---------------------------------------------------------------------------
__global__ __launch_bounds__(256) void setup_kernel(
    const float* __restrict__ gf,
    const float* __restrict__ cmW1, const float* __restrict__ cmb1,
    const float* __restrict__ cmW2,
    const void* __restrict__ cube_mask, const void* __restrict__ group_mask,
    const int* __restrict__ atm)
{
    const int t = threadIdx.x;
    if (blockIdx.x == B_) {
        const int n = t & 127, kh = (t >> 7) * 32;
        const float* wp = cmW1 + n;
        #pragma unroll 8
        for (int kk = 0; kk < 32; kk++) {
            int k2 = kh + kk;
            float w0 = __ldg(wp + (2 * k2) * 128);
            float w1 = __ldg(wp + (2 * k2 + 1) * 128);
            d_W1bf[n * 68 + k2] = bf2(w0, w1);
        }
        for (int idx = t; idx < 24 * 64; idx += 256) {
            int nn = idx % 24, kk = idx / 24;
            float w0 = __ldg(cmW2 + (2 * kk) * 24 + nn);
            float w1 = __ldg(cmW2 + (2 * kk + 1) * 24 + nn);
            d_W2bf[nn * 68 + kk] = bf2(w0, w1);
        }
        return;
    }

    const int b = blockIdx.x;
    const int w = t >> 5, lane = t & 31;
    const int mode = mask_mode(atm);
    __shared__ float g[128];
    __shared__ float sred[4][128];
    __shared__ int wtc[4], wtg[4], stc, stg;

    if (t < 128) g[t] = gf[b * 128 + t];
    __syncthreads();

    unsigned cm8 = 0, gm8 = 0;
    int cex = 0, gex = 0;

    if (w < 4) {
        const float4* W4 = (const float4*)cmW1;
        float4 a = make_float4(0.f, 0.f, 0.f, 0.f);
        #pragma unroll
        for (int kk = 0; kk < 32; kk++) {
            int k = 32 * w + kk;
            float4 wv = __ldg(&W4[(128 + k) * 32 + lane]);
            float gk = g[k];
            a.x = fmaf(gk, wv.x, a.x);
            a.y = fmaf(gk, wv.y, a.y);
            a.z = fmaf(gk, wv.z, a.z);
            a.w = fmaf(gk, wv.w, a.w);
        }
        *(float4*)&sred[w][4 * lane] = a;
    } else if (mode == 1) {
        const int w4 = w - 4;
        const int4* cm4 = (const int4*)cube_mask + b * 256 + w4 * 64 + lane * 2;
        const int4* gm4 = (const int4*)group_mask + b * 256 + w4 * 64 + lane * 2;
        int4 c0 = __ldg(cm4), c1 = __ldg(cm4 + 1);
        int4 g0 = __ldg(gm4), g1 = __ldg(gm4 + 1);
        cm8 = (c0.x != 0) | ((c0.y != 0) << 1) | ((c0.z != 0) << 2) | ((c0.w != 0) << 3)
            | ((c1.x != 0) << 4) | ((c1.y != 0) << 5) | ((c1.z != 0) << 6) | ((c1.w != 0) << 7);
        gm8 = (g0.x != 0) | ((g0.y != 0) << 1) | ((g0.z != 0) << 2) | ((g0.w != 0) << 3)
            | ((g1.x != 0) << 4) | ((g1.y != 0) << 5) | ((g1.z != 0) << 6) | ((g1.w != 0) << 7);
        int cs = __popc(cm8), gs = __popc(gm8);
        int csi = cs, gsi = gs;
        #pragma unroll
        for (int off = 1; off < 32; off <<= 1) {
            int v1 = __shfl_up_sync(0xffffffffu, csi, off);
            int v2 = __shfl_up_sync(0xffffffffu, gsi, off);
            if (lane >= off) { csi += v1; gsi += v2; }
        }
        cex = csi - cs; gex = gsi - gs;
        if (lane == 31) { wtc[w4] = csi; wtg[w4] = gsi; }
    } else if (w == 4) {
        int cc = 0, gc = 0;
        for (int c = 0; c < NPG; c += 32) {
            long node = (long)b * NPG + c + lane;
            bool cm = read_mask(cube_mask, node, mode);
            bool gm = read_mask(group_mask, node, mode);
            unsigned cb = __ballot_sync(0xffffffffu, cm);
            unsigned gb = __ballot_sync(0xffffffffu, gm);
            unsigned lt = (1u << lane) - 1u;
            if (cm) { int p = cc + __popc(cb & lt); if (p < MAXC) d_cube_node[b * MAXC + p] = (int)node; }
            if (gm) { int p = gc + __popc(gb & lt); if (p < G_)   d_group_node[b * G_ + p] = (int)node; }
            cc += __popc(cb);
            gc += __popc(gb);
        }
        if (lane == 0) { stc = cc; stg = gc; }
    }
    __syncthreads();

    if (t < 128)
        d_cm_gc[b * 128 + t] = __ldg(cmb1 + t) +
            ((sred[0][t] + sred[1][t]) + (sred[2][t] + sred[3][t]));

    int tc, tg;
    if (mode == 1) {
        tc = wtc[0] + wtc[1] + wtc[2] + wtc[3];
        tg = wtg[0] + wtg[1] + wtg[2] + wtg[3];
        if (w >= 4) {
            const int w4 = w - 4;
            int cbase = 0, gbase = 0;
            #pragma unroll
            for (int i = 0; i < 4; i++) if (i < w4) { cbase += wtc[i]; gbase += wtg[i]; }
            const int nb = b * NPG + w4 * 256 + lane * 8;
            #pragma unroll
            for (int j = 0; j < 8; j++) {
                if ((cm8 >> j) & 1) {
                    int p = cbase + cex + __popc(cm8 & ((1u << j) - 1u));
                    if (p < MAXC) d_cube_node[b * MAXC + p] = nb + j;
                }
                if ((gm8 >> j) & 1) {
                    int p = gbase + gex + __popc(gm8 & ((1u << j) - 1u));
                    if (p < G_) d_group_node[b * G_ + p] = nb + j;
                }
            }
        }
    } else {
        tc = stc; tg = stg;
    }
    for (int p = tc + t; p < MAXC; p += 256) d_cube_node[b * MAXC + p] = -1;
    for (int p = tg + t; p < G_; p += 256)   d_group_node[b * G_ + p] = -1;
}

// ---------------------------------------------------------------------------
// mega kernel, 256 threads/block, 3 blocks/SM:
//   blocks 0-511 cube (mma.sync bf16 + ldmatrix), 512-639 dock, 640-767 man+AT
// cube dyn smem: Xs 0..34816 | Ws1 ..69632 | Ws2 ..76160 | nodes ..76672
// ---------------------------------------------------------------------------
constexpr int SMEM_DYN = 76672;

__global__ __launch_bounds__(256, 3) void mega_kernel(
    const float* __restrict__ nodef, const float* __restrict__ gf,
    const int* __restrict__ atm, const void* __restrict__ move_mask,
    const void* __restrict__ dvm, const void* __restrict__ mvm,
    const float* __restrict__ cm_b2,
    const float* __restrict__ at_W1, const float* __restrict__ at_b1,
    const float* __restrict__ at_W2, const float* __restrict__ at_b2,
    const float* __restrict__ dk_W1, const float* __restrict__ dk_b1,
    const float* __restrict__ dk_W2, const float* __restrict__ dk_b2,
    const float* __restrict__ dk_W3, const float* __restrict__ dk_b3,
    const float* __restrict__ mn_W1, const float* __restrict__ mn_b1,
    const float* __restrict__ mn_W2, const float* __restrict__ mn_b2,
    float* __restrict__ out_at, float* __restrict__ out_cube,
    float* __restrict__ out_dock, float* __restrict__ out_man)
{
    extern __shared__ __align__(16) char smem_raw[];
    const int t = threadIdx.x;
    const int mode = mask_mode(atm);

    if (blockIdx.x < 512) {
        // ===================== CUBE =====================
        uint32_t* Xs  = (uint32_t*)smem_raw;                 // [128][68] bf16x2, k-major
        uint32_t* Ws1 = (uint32_t*)(smem_raw + 34816);       // [128n][68]
        uint32_t* Ws2 = (uint32_t*)(smem_raw + 69632);       // [24n][68]
        int*   nodes = (int*)(smem_raw + 76160);

        const int row0 = blockIdx.x * 128;
        const int b = row0 >> 9;
        const int w = t >> 5, lane = t & 31;
        const int gid4 = lane >> 2, tig = lane & 3;

        // W images: coalesced uint4 copies from precomputed globals (L2-hot)
        {
            const uint4* src1 = (const uint4*)d_W1bf;
            uint4* dst1 = (uint4*)Ws1;
            #pragma unroll
            for (int i = 0; i < 8; i++) dst1[t + i * 256] = src1[t + i * 256];
            if (t < 128) dst1[t + 2048] = src1[t + 2048];
            const uint4* src2 = (const uint4*)d_W2bf;
            uint4* dst2 = (uint4*)Ws2;
            if (t < 204) { dst2[t] = src2[t]; dst2[t + 204] = src2[t + 204]; }
        }
        if (t < 128) nodes[t] = d_cube_node[row0 + t];
        // X: warp-per-row, lane <-> float4 of row (coalesced), k-major bf16x2
        #pragma unroll
        for (int i = 0; i < 16; i++) {
            int r = 16 * w + i;
            int nd = __ldg(&d_cube_node[row0 + r]);
            uint64_t v = 0ull;
            if (nd >= 0) {
                float4 x = __ldg((const float4*)(nodef + (size_t)nd * 128) + lane);
                v = ((uint64_t)bf2(x.z, x.w) << 32) | (uint64_t)bf2(x.x, x.y);
            }
            *(uint64_t*)&Xs[r * 68 + 2 * lane] = v;
        }
        __syncthreads();

        const int ar0 = 16 * w + gid4;
        const float* gcp = d_cm_gc + b * 128;

        // ldmatrix addresses (byte-based shared addresses); row stride 272B
        const int mi = lane >> 3, ri = lane & 7;
        const uint32_t xadr = smem_u32(Xs) + (uint32_t)((16 * w + ri + 8 * (mi & 1)) * 272 + (mi >> 1) * 16);
        const uint32_t badr = smem_u32(Ws1) + (uint32_t)(((mi >> 1) * 8 + ri) * 272 + (mi & 1) * 16);
        const uint32_t b2adr  = smem_u32(Ws2) + (uint32_t)(((mi >> 1) * 8 + ri) * 272 + (mi & 1) * 16);
        const uint32_t b2adr2 = smem_u32(Ws2) + (uint32_t)((16 + ri) * 272 + ((lane >> 3) & 1) * 16);

        float acc[8][4];
        uint32_t h0[16];

        // ---- GEMM1 pass 0: out cols 0..63 ----
        #pragma unroll
        for (int i = 0; i < 8; i++)
            #pragma unroll
            for (int j = 0; j < 4; j++) acc[i][j] = 0.f;
        #pragma unroll
        for (int ks = 0; ks < 8; ks++) {
            uint32_t a0, a1, a2, a3;
            ldsm4(a0, a1, a2, a3, xadr + ks * 32);
            #pragma unroll
            for (int p = 0; p < 4; p++) {
                uint32_t b0, b1, b2, b3;
                ldsm4(b0, b1, b2, b3, badr + p * 4352 + ks * 32);
                mma16816(acc[2 * p],     a0, a1, a2, a3, b0, b1);
                mma16816(acc[2 * p + 1], a0, a1, a2, a3, b2, b3);
            }
        }
        #pragma unroll
        for (int nt = 0; nt < 8; nt++) {
            int c0 = 8 * nt + 2 * tig;
            float g0 = __ldg(gcp + c0), g1 = __ldg(gcp + c0 + 1);
            h0[nt]     = bf2(fmaxf(acc[nt][0] + g0, 0.f), fmaxf(acc[nt][1] + g1, 0.f));
            h0[nt + 8] = bf2(fmaxf(acc[nt][2] + g0, 0.f), fmaxf(acc[nt][3] + g1, 0.f));
        }

        // ---- GEMM1 pass 1: out cols 64..127 ----
        #pragma unroll
        for (int i = 0; i < 8; i++)
            #pragma unroll
            for (int j = 0; j < 4; j++) acc[i][j] = 0.f;
        #pragma unroll
        for (int ks = 0; ks < 8; ks++) {
            uint32_t a0, a1, a2, a3;
            ldsm4(a0, a1, a2, a3, xadr + ks * 32);
            #pragma unroll
            for (int p = 0; p < 4; p++) {
                uint32_t b0, b1, b2, b3;
                ldsm4(b0, b1, b2, b3, badr + 17408 + p * 4352 + ks * 32);
                mma16816(acc[2 * p],     a0, a1, a2, a3, b0, b1);
                mma16816(acc[2 * p + 1], a0, a1, a2, a3, b2, b3);
            }
        }
        // write H (both halves) over A rows, k-major (all A reads complete)
        #pragma unroll
        for (int nt = 0; nt < 8; nt++) {
            int c1 = 64 + 8 * nt + 2 * tig;
            float g0 = __ldg(gcp + c1), g1 = __ldg(gcp + c1 + 1);
            Xs[ar0 * 68 + 4 * nt + tig]            = h0[nt];
            Xs[(ar0 + 8) * 68 + 4 * nt + tig]      = h0[nt + 8];
            Xs[ar0 * 68 + 32 + 4 * nt + tig]       = bf2(fmaxf(acc[nt][0] + g0, 0.f), fmaxf(acc[nt][1] + g1, 0.f));
            Xs[(ar0 + 8) * 68 + 32 + 4 * nt + tig] = bf2(fmaxf(acc[nt][2] + g0, 0.f), fmaxf(acc[nt][3] + g1, 0.f));
        }
        __syncwarp();

        // GEMM2: H @ W2^T (N=24)
        float acc2[3][4];
        #pragma unroll
        for (int i = 0; i < 3; i++)
            #pragma unroll
            for (int j = 0; j < 4; j++) acc2[i][j] = 0.f;
        #pragma unroll
        for (int ks = 0; ks < 8; ks++) {
            uint32_t a0, a1, a2, a3;
            ldsm4(a0, a1, a2, a3, xadr + ks * 32);
            uint32_t b0, b1, b2, b3, e0r, e1r;
            ldsm4(b0, b1, b2, b3, b2adr + ks * 32);
            ldsm2(e0r, e1r, b2adr2 + ks * 32);
            mma16816(acc2[0], a0, a1, a2, a3, b0, b1);
            mma16816(acc2[1], a0, a1, a2, a3, b2, b3);
            mma16816(acc2[2], a0, a1, a2, a3, e0r, e1r);
        }
        __syncwarp();   // warp's Xs reads done before overwrite as D-stage

        // stage D2+bias into warp-own region of Xs (384 floats)
        float* Dw = (float*)(Xs + (16 * w) * 68);
        #pragma unroll
        for (int nt = 0; nt < 3; nt++) {
            int c0 = 8 * nt + 2 * tig;
            float bb0 = __ldg(cm_b2 + c0), bb1 = __ldg(cm_b2 + c0 + 1);
            Dw[gid4 * 24 + c0]           = acc2[nt][0] + bb0;
            Dw[gid4 * 24 + c0 + 1]       = acc2[nt][1] + bb1;
            Dw[(gid4 + 8) * 24 + c0]     = acc2[nt][2] + bb0;
            Dw[(gid4 + 8) * 24 + c0 + 1] = acc2[nt][3] + bb1;
        }
        __syncwarp();

        // warp-local masked vector write: 96 float4
        const long e0 = (long)(row0 + 16 * w) * 24;
        #pragma unroll
        for (int j = 0; j < 3; j++) {
            int idx4 = j * 32 + lane;
            float4 v = ((const float4*)Dw)[idx4];
            float r4[4] = {v.x, v.y, v.z, v.w};
            float o4[4];
            if (mode == 1) {
                int4 mk = __ldg((const int4*)move_mask + (e0 >> 2) + idx4);
                int m4[4] = {mk.x, mk.y, mk.z, mk.w};
                #pragma unroll
                for (int q = 0; q < 4; q++) {
                    int e = idx4 * 4 + q;
                    bool ok = (nodes[16 * w + e / 24] >= 0) && (m4[q] != 0);
                    o4[q] = ok ? r4[q] : NEG;
                }
            } else {
                #pragma unroll
                for (int q = 0; q < 4; q++) {
                    int e = idx4 * 4 + q;
                    bool ok = (nodes[16 * w + e / 24] >= 0) && read_mask(move_mask, e0 + e, mode);
                    o4[q] = ok ? r4[q] : NEG;
                }
            }
            *(float4*)(out_cube + e0 + idx4 * 4) = make_float4(o4[0], o4[1], o4[2], o4[3]);
        }
        return;
    }

    // ===================== HEADS =====================
    const int hb = blockIdx.x - 512;
    const int b = hb & 127;
    if (hb < 128) {
        // ---------- DOCKING ----------
        float* gf8 = (float*)smem_raw;
        float* gl  = (float*)(smem_raw + 4096);
        float* uu  = (float*)(smem_raw + 4608);
        float* vv  = (float*)(smem_raw + 8704);
        float* ww  = (float*)(smem_raw + 12800);
        float* W3s = (float*)(smem_raw + 13312);
        int*   gid = (int*)  (smem_raw + 13568);
        float* W2s = (float*)(smem_raw + 13600);

        if (t < G_) gid[t] = d_group_node[b * G_ + t];
        if (t >= 128) gl[t - 128] = gf[b * 128 + (t - 128)];
        __syncthreads();
        #pragma unroll
        for (int i = 0; i < 4; i++) {
            int idx = t + i * 256;
            int g = idx >> 7, c = idx & 127;
            int n = gid[g];
            gf8[g * 128 + c] = (n >= 0) ? __ldg(nodef + (size_t)n * 128 + c) : 0.f;
        }
        #pragma unroll
        for (int i = 0; i < 32; i++) W2s[t + i * 256] = __ldg(dk_W2 + t + i * 256);
        if (t < 64) W3s[t] = __ldg(dk_W3 + t);
        __syncthreads();

        if (t < 128) {
            float ua[G_], va[G_];
            #pragma unroll
            for (int g = 0; g < G_; g++) { ua[g] = 0.f; va[g] = 0.f; }
            float wv = __ldg(dk_b1 + t);
            #pragma unroll 4
            for (int k = 0; k < 128; k++) {
                float wa = __ldg(dk_W1 + k * 128 + t);
                float wb = __ldg(dk_W1 + (128 + k) * 128 + t);
                float wc = __ldg(dk_W1 + (256 + k) * 128 + t);
                #pragma unroll
                for (int g = 0; g < G_; g++) {
                    float x = gf8[g * 128 + k];
                    ua[g] = fmaf(x, wa, ua[g]);
                    va[g] = fmaf(x, wb, va[g]);
                }
                wv = fmaf(gl[k], wc, wv);
            }
            #pragma unroll
            for (int g = 0; g < G_; g++) { uu[g * 128 + t] = ua[g]; vv[g * 128 + t] = va[g]; }
            ww[t] = wv;
        }
        __syncthreads();

        const int wp = t >> 5, lane = t & 31;
        const float b2a = __ldg(dk_b2 + lane);
        const float b2b = __ldg(dk_b2 + lane + 32);
        const float b3v = __ldg(dk_b3);
        const float w3a = W3s[lane], w3b = W3s[lane + 32];

        #pragma unroll
        for (int jj = 0; jj < 2; jj++) {
            const int p0 = wp + 16 * jj;
            const int p1r = p0 + 8;
            const bool has1 = p1r < P_;
            const int p1 = has1 ? p1r : p0;
            const int i0 = c_IU[p0], j0 = c_JU[p0];
            const int i1 = c_IU[p1], j1 = c_JU[p1];
            float s0a = 0.f, s0b = 0.f, s1a = 0.f, s1b = 0.f;
            #pragma unroll 4
            for (int k = 0; k < 128; k++) {
                float wk = ww[k];
                float h0 = fmaxf(uu[i0 * 128 + k] + vv[j0 * 128 + k] + wk, 0.f);
                float h1 = fmaxf(uu[i1 * 128 + k] + vv[j1 * 128 + k] + wk, 0.f);
                float w2a = W2s[k * 64 + lane];
                float w2b = W2s[k * 64 + lane + 32];
                s0a = fmaf(h0, w2a, s0a);
                s0b = fmaf(h0, w2b, s0b);
                s1a = fmaf(h1, w2a, s1a);
                s1b = fmaf(h1, w2b, s1b);
            }
            float c0 = fmaxf(s0a + b2a, 0.f) * w3a + fmaxf(s0b + b2b, 0.f) * w3b;
            float c1 = fmaxf(s1a + b2a, 0.f) * w3a + fmaxf(s1b + b2b, 0.f) * w3b;
            #pragma unroll
            for (int off = 16; off; off >>= 1) {
                c0 += __shfl_down_sync(0xffffffffu, c0, off);
                c1 += __shfl_down_sync(0xffffffffu, c1, off);
            }
            if (lane == 0) {
                bool ok0 = read_mask(dvm, b * P_ + p0, mode) && gid[i0] >= 0 && gid[j0] >= 0;
                out_dock[b * P_ + p0] = ok0 ? (c0 + b3v) : NEG;
                if (has1) {
                    bool ok1 = read_mask(dvm, b * P_ + p1, mode) && gid[i1] >= 0 && gid[j1] >= 0;
                    out_dock[b * P_ + p1] = ok1 ? (c1 + b3v) : NEG;
                }
            }
        }
    } else {
        // ---------- MANEUVER + ACTION TYPE ----------
        float* gf8  = (float*)smem_raw;
        float* gl   = (float*)(smem_raw + 4096);
        float* manH = (float*)(smem_raw + 4608);
        float* ath  = (float*)(smem_raw + 8704);
        float* W2m  = (float*)(smem_raw + 8960);
        int*   gid  = (int*)  (smem_raw + 12544);

        if (t < G_) gid[t] = d_group_node[b * G_ + t];
        if (t >= 128) gl[t - 128] = gf[b * 128 + (t - 128)];
        __syncthreads();
        #pragma unroll
        for (int i = 0; i < 4; i++) {
            int idx = t + i * 256;
            int g = idx >> 7, c = idx & 127;
            int n = gid[g];
            gf8[g * 128 + c] = (n >= 0) ? __ldg(nodef + (size_t)n * 128 + c) : 0.f;
        }
        for (int idx = t; idx < 128 * ND_; idx += 256) W2m[idx] = __ldg(mn_W2 + idx);
        __syncthreads();

        if (t < 128) {
            float ma[G_];
            #pragma unroll
            for (int g = 0; g < G_; g++) ma[g] = 0.f;
            float gcm = __ldg(mn_b1 + t);
            float av = (t < 64) ? __ldg(at_b1 + t) : 0.f;
            #pragma unroll 4
            for (int k = 0; k < 128; k++) {
                float wa = __ldg(mn_W1 + k * 128 + t);
                float wb = __ldg(mn_W1 + (128 + k) * 128 + t);
                float gk = gl[k];
                #pragma unroll
                for (int g = 0; g < G_; g++) ma[g] = fmaf(gf8[g * 128 + k], wa, ma[g]);
                gcm = fmaf(gk, wb, gcm);
                if (t < 64) av = fmaf(gk, __ldg(at_W1 + k * 64 + t), av);
            }
            #pragma unroll
            for (int g = 0; g < G_; g++) manH[g * 128 + t] = fmaxf(ma[g] + gcm, 0.f);
            if (t < 64) ath[t] = fmaxf(av, 0.f);
        }
        __syncthreads();

        if (t < G_ * ND_) {
            int g = t / ND_, d = t - g * ND_;
            float s = __ldg(mn_b2 + d);
            #pragma unroll 8
            for (int k = 0; k < 128; k++) s = fmaf(manH[g * 128 + k], W2m[k * ND_ + d], s);
            bool ok = (gid[g] >= 0) && read_mask(mvm, b * G_ * ND_ + t, mode);
            out_man[b * G_ * ND_ + t] = ok ? s : NEG;
        } else if (t >= 64 && t < 64 + AT_) {
            int a = t - 64;
            float s = __ldg(at_b2 + a);
            #pragma unroll 8
            for (int k = 0; k < 64; k++) s = fmaf(ath[k], __ldg(at_W2 + k * AT_ + a), s);
            out_at[b * AT_ + a] = read_mask(atm, b * AT_ + a, mode) ? s : NEG;
        }
    }
}

// ---------------------------------------------------------------------------
extern "C" void kernel_launch(void* const* d_in, const int* in_sizes, int n_in,
                              void* d_out, int out_size) {
    const float* nodef      = (const float*)d_in[0];
    const float* gf         = (const float*)d_in[1];
    const int*   atm        = (const int*)d_in[2];
    const void*  cube_mask  = d_in[3];
    const void*  group_mask = d_in[4];
    /* d_in[5] = batch (unused; segments contiguous) */
    const void*  move_mask  = d_in[6];
    const void*  dvm        = d_in[7];
    const void*  mvm        = d_in[8];
    const float* at_W1 = (const float*)d_in[9];
    const float* at_b1 = (const float*)d_in[10];
    const float* at_W2 = (const float*)d_in[11];
    const float* at_b2 = (const float*)d_in[12];
    const float* cm_W1 = (const float*)d_in[13];
    const float* cm_b1 = (const float*)d_in[14];
    const float* cm_W2 = (const float*)d_in[15];
    const float* cm_b2 = (const float*)d_in[16];
    const float* dk_W1 = (const float*)d_in[17];
    const float* dk_b1 = (const float*)d_in[18];
    const float* dk_W2 = (const float*)d_in[19];
    const float* dk_b2 = (const float*)d_in[20];
    const float* dk_W3 = (const float*)d_in[21];
    const float* dk_b3 = (const float*)d_in[22];
    const float* mn_W1 = (const float*)d_in[23];
    const float* mn_b1 = (const float*)d_in[24];
    const float* mn_W2 = (const float*)d_in[25];
    const float* mn_b2 = (const float*)d_in[26];

    float* out      = (float*)d_out;
    float* out_at   = out;
    float* out_cube = out + (size_t)B_ * AT_;
    float* out_dock = out_cube + (size_t)B_ * MAXC * M_;
    float* out_man  = out_dock + (size_t)B_ * P_;

    cudaFuncSetAttribute(mega_kernel, cudaFuncAttributeMaxDynamicSharedMemorySize, SMEM_DYN);

    setup_kernel<<<B_ + 1, 256>>>(gf, cm_W1, cm_b1, cm_W2, cube_mask, group_mask, atm);
    mega_kernel<<<768, 256, SMEM_DYN>>>(
        nodef, gf, atm, move_mask, dvm, mvm,
        cm_b2,
        at_W1, at_b1, at_W2, at_b2,
        dk_W1, dk_b1, dk_W2, dk_b2, dk_W3, dk_b3,
        mn_W1, mn_b1, mn_W2, mn_b2,
        out_at, out_cube, out_dock, out_man);
}

// round 14
// speedup vs baseline: 1.2471x; 1.1490x over previous
#include <cuda_runtime.h>
#include <cuda_bf16.h>
#include <stdint.h>

#define NEG (-1e9f)
constexpr int B_   = 128;
constexpr int NPG  = 1024;
constexpr int M_   = 24;
constexpr int MAXC = 512;
constexpr int G_   = 8;
constexpr int ND_  = 7;
constexpr int AT_  = 5;
constexpr int P_   = 28;

__device__ int      d_cube_node[B_ * MAXC];
__device__ int      d_group_node[B_ * G_];
__device__ float    d_cm_gc[B_ * 128];
__device__ uint32_t d_W1bf[128 * 68];   // bf16x2 W1^T image (n-major, stride 68 u32)
__device__ uint32_t d_W2bf[24 * 68];    // bf16x2 W2^T image

__constant__ int c_IU[P_] = {0,0,0,0,0,0,0,1,1,1,1,1,1,2,2,2,2,2,3,3,3,3,4,4,4,5,5,6};
__constant__ int c_JU[P_] = {1,2,3,4,5,6,7,2,3,4,5,6,7,3,4,5,6,7,4,5,6,7,5,6,7,6,7,7};

__device__ __forceinline__ int mask_mode(const int* __restrict__ atm) {
    int v = __ldg(atm);
    if (v == 1) return 1;
    if (v == 0x3F800000) return 2;
    return 0;
}
__device__ __forceinline__ bool read_mask(const void* p, long i, int mode) {
    if (mode == 1) return ((const int*)p)[i] != 0;
    if (mode == 2) return ((const float*)p)[i] != 0.f;
    return ((const uint8_t*)p)[i] != 0;
}

// bf16 mma.sync (sm_80+ baseline PTX -> HMMA on sm_103)
__device__ __forceinline__ void mma16816(float* c, uint32_t a0, uint32_t a1,
                                         uint32_t a2, uint32_t a3,
                                         uint32_t b0, uint32_t b1) {
    asm volatile(
        "mma.sync.aligned.m16n8k16.row.col.f32.bf16.bf16.f32 "
        "{%0,%1,%2,%3}, {%4,%5,%6,%7}, {%8,%9}, {%0,%1,%2,%3};"
        : "+f"(c[0]), "+f"(c[1]), "+f"(c[2]), "+f"(c[3])
        : "r"(a0), "r"(a1), "r"(a2), "r"(a3), "r"(b0), "r"(b1));
}
__device__ __forceinline__ uint32_t bf2(float x, float y) {
    __nv_bfloat162 p = __float22bfloat162_rn(make_float2(x, y));
    return *(uint32_t*)&p;
}

// ---------------------------------------------------------------------------
// setup: blocks 0..127 per-batch work; block 128 converts cube weights to bf16
// ---------------------------------------------------------------------------
__global__ __launch_bounds__(256) void setup_kernel(
    const float* __restrict__ gf,
    const float* __restrict__ cmW1, const float* __restrict__ cmb1,
    const float* __restrict__ cmW2,
    const void* __restrict__ cube_mask, const void* __restrict__ group_mask,
    const int* __restrict__ atm)
{
    const int t = threadIdx.x;
    if (blockIdx.x == B_) {
        const int n = t & 127, kh = (t >> 7) * 32;
        const float* wp = cmW1 + n;
        #pragma unroll 8
        for (int kk = 0; kk < 32; kk++) {
            int k2 = kh + kk;
            float w0 = __ldg(wp + (2 * k2) * 128);
            float w1 = __ldg(wp + (2 * k2 + 1) * 128);
            d_W1bf[n * 68 + k2] = bf2(w0, w1);
        }
        for (int idx = t; idx < 24 * 64; idx += 256) {
            int nn = idx % 24, kk = idx / 24;
            float w0 = __ldg(cmW2 + (2 * kk) * 24 + nn);
            float w1 = __ldg(cmW2 + (2 * kk + 1) * 24 + nn);
            d_W2bf[nn * 68 + kk] = bf2(w0, w1);
        }
        return;
    }

    const int b = blockIdx.x;
    const int w = t >> 5, lane = t & 31;
    const int mode = mask_mode(atm);
    __shared__ float g[128];
    __shared__ float sred[4][128];
    __shared__ int wtc[4], wtg[4], stc, stg;

    if (t < 128) g[t] = gf[b * 128 + t];
    __syncthreads();

    unsigned cm8 = 0, gm8 = 0;
    int cex = 0, gex = 0;

    if (w < 4) {
        const float4* W4 = (const float4*)cmW1;
        float4 a = make_float4(0.f, 0.f, 0.f, 0.f);
        #pragma unroll
        for (int kk = 0; kk < 32; kk++) {
            int k = 32 * w + kk;
            float4 wv = __ldg(&W4[(128 + k) * 32 + lane]);
            float gk = g[k];
            a.x = fmaf(gk, wv.x, a.x);
            a.y = fmaf(gk, wv.y, a.y);
            a.z = fmaf(gk, wv.z, a.z);
            a.w = fmaf(gk, wv.w, a.w);
        }
        *(float4*)&sred[w][4 * lane] = a;
    } else if (mode == 1) {
        const int w4 = w - 4;
        const int4* cm4 = (const int4*)cube_mask + b * 256 + w4 * 64 + lane * 2;
        const int4* gm4 = (const int4*)group_mask + b * 256 + w4 * 64 + lane * 2;
        int4 c0 = __ldg(cm4), c1 = __ldg(cm4 + 1);
        int4 g0 = __ldg(gm4), g1 = __ldg(gm4 + 1);
        cm8 = (c0.x != 0) | ((c0.y != 0) << 1) | ((c0.z != 0) << 2) | ((c0.w != 0) << 3)
            | ((c1.x != 0) << 4) | ((c1.y != 0) << 5) | ((c1.z != 0) << 6) | ((c1.w != 0) << 7);
        gm8 = (g0.x != 0) | ((g0.y != 0) << 1) | ((g0.z != 0) << 2) | ((g0.w != 0) << 3)
            | ((g1.x != 0) << 4) | ((g1.y != 0) << 5) | ((g1.z != 0) << 6) | ((g1.w != 0) << 7);
        int cs = __popc(cm8), gs = __popc(gm8);
        int csi = cs, gsi = gs;
        #pragma unroll
        for (int off = 1; off < 32; off <<= 1) {
            int v1 = __shfl_up_sync(0xffffffffu, csi, off);
            int v2 = __shfl_up_sync(0xffffffffu, gsi, off);
            if (lane >= off) { csi += v1; gsi += v2; }
        }
        cex = csi - cs; gex = gsi - gs;
        if (lane == 31) { wtc[w4] = csi; wtg[w4] = gsi; }
    } else if (w == 4) {
        int cc = 0, gc = 0;
        for (int c = 0; c < NPG; c += 32) {
            long node = (long)b * NPG + c + lane;
            bool cm = read_mask(cube_mask, node, mode);
            bool gm = read_mask(group_mask, node, mode);
            unsigned cb = __ballot_sync(0xffffffffu, cm);
            unsigned gb = __ballot_sync(0xffffffffu, gm);
            unsigned lt = (1u << lane) - 1u;
            if (cm) { int p = cc + __popc(cb & lt); if (p < MAXC) d_cube_node[b * MAXC + p] = (int)node; }
            if (gm) { int p = gc + __popc(gb & lt); if (p < G_)   d_group_node[b * G_ + p] = (int)node; }
            cc += __popc(cb);
            gc += __popc(gb);
        }
        if (lane == 0) { stc = cc; stg = gc; }
    }
    __syncthreads();

    if (t < 128)
        d_cm_gc[b * 128 + t] = __ldg(cmb1 + t) +
            ((sred[0][t] + sred[1][t]) + (sred[2][t] + sred[3][t]));

    int tc, tg;
    if (mode == 1) {
        tc = wtc[0] + wtc[1] + wtc[2] + wtc[3];
        tg = wtg[0] + wtg[1] + wtg[2] + wtg[3];
        if (w >= 4) {
            const int w4 = w - 4;
            int cbase = 0, gbase = 0;
            #pragma unroll
            for (int i = 0; i < 4; i++) if (i < w4) { cbase += wtc[i]; gbase += wtg[i]; }
            const int nb = b * NPG + w4 * 256 + lane * 8;
            #pragma unroll
            for (int j = 0; j < 8; j++) {
                if ((cm8 >> j) & 1) {
                    int p = cbase + cex + __popc(cm8 & ((1u << j) - 1u));
                    if (p < MAXC) d_cube_node[b * MAXC + p] = nb + j;
                }
                if ((gm8 >> j) & 1) {
                    int p = gbase + gex + __popc(gm8 & ((1u << j) - 1u));
                    if (p < G_) d_group_node[b * G_ + p] = nb + j;
                }
            }
        }
    } else {
        tc = stc; tg = stg;
    }
    for (int p = tc + t; p < MAXC; p += 256) d_cube_node[b * MAXC + p] = -1;
    for (int p = tg + t; p < G_; p += 256)   d_group_node[b * G_ + p] = -1;
}

// ---------------------------------------------------------------------------
// mega kernel, 256 threads/block, 3 blocks/SM:
//   blocks 0-127 docking, 128-255 man+AT (long-latency heads FIRST),
//   blocks 256-767 cube (mma.sync bf16, R11 body)
// cube dyn smem: Xs 0..34816 | Ws1 ..69632 | Ws2 ..76160 | nodes ..76672
// ---------------------------------------------------------------------------
constexpr int SMEM_DYN = 76672;

__global__ __launch_bounds__(256, 3) void mega_kernel(
    const float* __restrict__ nodef, const float* __restrict__ gf,
    const int* __restrict__ atm, const void* __restrict__ move_mask,
    const void* __restrict__ dvm, const void* __restrict__ mvm,
    const float* __restrict__ cm_b2,
    const float* __restrict__ at_W1, const float* __restrict__ at_b1,
    const float* __restrict__ at_W2, const float* __restrict__ at_b2,
    const float* __restrict__ dk_W1, const float* __restrict__ dk_b1,
    const float* __restrict__ dk_W2, const float* __restrict__ dk_b2,
    const float* __restrict__ dk_W3, const float* __restrict__ dk_b3,
    const float* __restrict__ mn_W1, const float* __restrict__ mn_b1,
    const float* __restrict__ mn_W2, const float* __restrict__ mn_b2,
    float* __restrict__ out_at, float* __restrict__ out_cube,
    float* __restrict__ out_dock, float* __restrict__ out_man)
{
    extern __shared__ __align__(16) char smem_raw[];
    const int t = threadIdx.x;
    const int mode = mask_mode(atm);

    if (blockIdx.x >= 256) {
        // ===================== CUBE (R11 body) =====================
        uint32_t* Xs  = (uint32_t*)smem_raw;                 // [128][68] bf16x2
        uint32_t* Ws1 = (uint32_t*)(smem_raw + 34816);
        uint32_t* Ws2 = (uint32_t*)(smem_raw + 69632);
        int*   nodes = (int*)(smem_raw + 76160);

        const int row0 = (blockIdx.x - 256) * 128;
        const int b = row0 >> 9;
        const int w = t >> 5, lane = t & 31;
        const int gid4 = lane >> 2, tig = lane & 3;

        // W images: coalesced uint4 copies from precomputed globals (L2-hot)
        {
            const uint4* src1 = (const uint4*)d_W1bf;
            uint4* dst1 = (uint4*)Ws1;
            #pragma unroll
            for (int i = 0; i < 8; i++) dst1[t + i * 256] = src1[t + i * 256];
            if (t < 128) dst1[t + 2048] = src1[t + 2048];
            const uint4* src2 = (const uint4*)d_W2bf;
            uint4* dst2 = (uint4*)Ws2;
            if (t < 204) { dst2[t] = src2[t]; dst2[t + 204] = src2[t + 204]; }
        }
        if (t < 128) nodes[t] = d_cube_node[row0 + t];
        // X: warp-per-row, lane <-> float4 of row (coalesced)
        #pragma unroll
        for (int i = 0; i < 16; i++) {
            int r = 16 * w + i;
            int nd = __ldg(&d_cube_node[row0 + r]);
            uint64_t v = 0ull;
            if (nd >= 0) {
                float4 x = __ldg((const float4*)(nodef + (size_t)nd * 128) + lane);
                v = ((uint64_t)bf2(x.z, x.w) << 32) | (uint64_t)bf2(x.x, x.y);
            }
            *(uint64_t*)&Xs[r * 68 + 2 * lane] = v;
        }
        __syncthreads();

        const int ar0 = 16 * w + gid4;
        const uint32_t* Xr0 = Xs + ar0 * 68 + tig;
        const uint32_t* Xr1 = Xs + (ar0 + 8) * 68 + tig;
        const float* gcp = d_cm_gc + b * 128;

        float acc[8][4];
        uint32_t h0[16];

        // ---- GEMM1 pass 0: out cols 0..63 ----
        #pragma unroll
        for (int i = 0; i < 8; i++)
            #pragma unroll
            for (int j = 0; j < 4; j++) acc[i][j] = 0.f;
        #pragma unroll
        for (int ks = 0; ks < 8; ks++) {
            uint32_t a0 = Xr0[8 * ks],     a1 = Xr1[8 * ks];
            uint32_t a2 = Xr0[8 * ks + 4], a3 = Xr1[8 * ks + 4];
            #pragma unroll
            for (int nt = 0; nt < 8; nt++) {
                const uint32_t* bp = Ws1 + (8 * nt + gid4) * 68 + 8 * ks + tig;
                mma16816(acc[nt], a0, a1, a2, a3, bp[0], bp[4]);
            }
        }
        #pragma unroll
        for (int nt = 0; nt < 8; nt++) {
            int c0 = 8 * nt + 2 * tig;
            float g0 = __ldg(gcp + c0), g1 = __ldg(gcp + c0 + 1);
            h0[nt]     = bf2(fmaxf(acc[nt][0] + g0, 0.f), fmaxf(acc[nt][1] + g1, 0.f));
            h0[nt + 8] = bf2(fmaxf(acc[nt][2] + g0, 0.f), fmaxf(acc[nt][3] + g1, 0.f));
        }

        // ---- GEMM1 pass 1: out cols 64..127 ----
        #pragma unroll
        for (int i = 0; i < 8; i++)
            #pragma unroll
            for (int j = 0; j < 4; j++) acc[i][j] = 0.f;
        #pragma unroll
        for (int ks = 0; ks < 8; ks++) {
            uint32_t a0 = Xr0[8 * ks],     a1 = Xr1[8 * ks];
            uint32_t a2 = Xr0[8 * ks + 4], a3 = Xr1[8 * ks + 4];
            #pragma unroll
            for (int nt = 0; nt < 8; nt++) {
                const uint32_t* bp = Ws1 + (64 + 8 * nt + gid4) * 68 + 8 * ks + tig;
                mma16816(acc[nt], a0, a1, a2, a3, bp[0], bp[4]);
            }
        }
        // write H (both halves) over A rows (all A reads complete)
        #pragma unroll
        for (int nt = 0; nt < 8; nt++) {
            int c1 = 64 + 8 * nt + 2 * tig;
            float g0 = __ldg(gcp + c1), g1 = __ldg(gcp + c1 + 1);
            Xs[ar0 * 68 + 4 * nt + tig]            = h0[nt];
            Xs[(ar0 + 8) * 68 + 4 * nt + tig]      = h0[nt + 8];
            Xs[ar0 * 68 + 32 + 4 * nt + tig]       = bf2(fmaxf(acc[nt][0] + g0, 0.f), fmaxf(acc[nt][1] + g1, 0.f));
            Xs[(ar0 + 8) * 68 + 32 + 4 * nt + tig] = bf2(fmaxf(acc[nt][2] + g0, 0.f), fmaxf(acc[nt][3] + g1, 0.f));
        }
        __syncwarp();

        // GEMM2: H @ W2^T (N=24)
        float acc2[3][4];
        #pragma unroll
        for (int i = 0; i < 3; i++)
            #pragma unroll
            for (int j = 0; j < 4; j++) acc2[i][j] = 0.f;
        #pragma unroll
        for (int ks = 0; ks < 8; ks++) {
            uint32_t a0 = Xr0[8 * ks],     a1 = Xr1[8 * ks];
            uint32_t a2 = Xr0[8 * ks + 4], a3 = Xr1[8 * ks + 4];
            #pragma unroll
            for (int nt = 0; nt < 3; nt++) {
                const uint32_t* bp = Ws2 + (8 * nt + gid4) * 68 + 8 * ks + tig;
                mma16816(acc2[nt], a0, a1, a2, a3, bp[0], bp[4]);
            }
        }
        __syncwarp();   // warp's Xs reads done before overwrite as D-stage

        // stage D2+bias into warp-own region of Xs (384 floats)
        float* Dw = (float*)(Xs + (16 * w) * 68);
        #pragma unroll
        for (int nt = 0; nt < 3; nt++) {
            int c0 = 8 * nt + 2 * tig;
            float bb0 = __ldg(cm_b2 + c0), bb1 = __ldg(cm_b2 + c0 + 1);
            Dw[gid4 * 24 + c0]           = acc2[nt][0] + bb0;
            Dw[gid4 * 24 + c0 + 1]       = acc2[nt][1] + bb1;
            Dw[(gid4 + 8) * 24 + c0]     = acc2[nt][2] + bb0;
            Dw[(gid4 + 8) * 24 + c0 + 1] = acc2[nt][3] + bb1;
        }
        __syncwarp();

        // warp-local masked vector write: 96 float4
        const long e0 = (long)(row0 + 16 * w) * 24;
        #pragma unroll
        for (int j = 0; j < 3; j++) {
            int idx4 = j * 32 + lane;
            float4 v = ((const float4*)Dw)[idx4];
            float r4[4] = {v.x, v.y, v.z, v.w};
            float o4[4];
            if (mode == 1) {
                int4 mk = __ldg((const int4*)move_mask + (e0 >> 2) + idx4);
                int m4[4] = {mk.x, mk.y, mk.z, mk.w};
                #pragma unroll
                for (int q = 0; q < 4; q++) {
                    int e = idx4 * 4 + q;
                    bool ok = (nodes[16 * w + e / 24] >= 0) && (m4[q] != 0);
                    o4[q] = ok ? r4[q] : NEG;
                }
            } else {
                #pragma unroll
                for (int q = 0; q < 4; q++) {
                    int e = idx4 * 4 + q;
                    bool ok = (nodes[16 * w + e / 24] >= 0) && read_mask(move_mask, e0 + e, mode);
                    o4[q] = ok ? r4[q] : NEG;
                }
            }
            *(float4*)(out_cube + e0 + idx4 * 4) = make_float4(o4[0], o4[1], o4[2], o4[3]);
        }
        return;
    }

    // ===================== HEADS (scheduled first) =====================
    const int b = blockIdx.x & 127;
    if (blockIdx.x < 128) {
        // ---------- DOCKING ----------
        float* gf8 = (float*)smem_raw;
        float* gl  = (float*)(smem_raw + 4096);
        float* uu  = (float*)(smem_raw + 4608);
        float* vv  = (float*)(smem_raw + 8704);
        float* ww  = (float*)(smem_raw + 12800);
        float* W3s = (float*)(smem_raw + 13312);
        int*   gid = (int*)  (smem_raw + 13568);
        float* W2s = (float*)(smem_raw + 13600);

        if (t < G_) gid[t] = d_group_node[b * G_ + t];
        if (t >= 128) gl[t - 128] = gf[b * 128 + (t - 128)];
        __syncthreads();
        #pragma unroll
        for (int i = 0; i < 4; i++) {
            int idx = t + i * 256;
            int g = idx >> 7, c = idx & 127;
            int n = gid[g];
            gf8[g * 128 + c] = (n >= 0) ? __ldg(nodef + (size_t)n * 128 + c) : 0.f;
        }
        #pragma unroll
        for (int i = 0; i < 32; i++) W2s[t + i * 256] = __ldg(dk_W2 + t + i * 256);
        if (t < 64) W3s[t] = __ldg(dk_W3 + t);
        __syncthreads();

        // hidden pass split over all 256 threads: t<128 -> u ; t>=128 -> v + w
        {
            const int half = t >> 7, tt = t & 127;
            float ua[G_];
            #pragma unroll
            for (int g = 0; g < G_; g++) ua[g] = 0.f;
            float wv = half ? __ldg(dk_b1 + tt) : 0.f;
            const float* Wbase = dk_W1 + (half ? 128 * 128 : 0) + tt;
            const float* Wc = dk_W1 + 256 * 128 + tt;
            #pragma unroll 4
            for (int k = 0; k < 128; k++) {
                float wa = __ldg(Wbase + k * 128);
                #pragma unroll
                for (int g = 0; g < G_; g++) ua[g] = fmaf(gf8[g * 128 + k], wa, ua[g]);
                if (half) wv = fmaf(gl[k], __ldg(Wc + k * 128), wv);
            }
            if (half == 0) {
                #pragma unroll
                for (int g = 0; g < G_; g++) uu[g * 128 + tt] = ua[g];
            } else {
                #pragma unroll
                for (int g = 0; g < G_; g++) vv[g * 128 + tt] = ua[g];
                ww[tt] = wv;
            }
        }
        __syncthreads();

        const int wp = t >> 5, lane = t & 31;
        const float b2a = __ldg(dk_b2 + lane);
        const float b2b = __ldg(dk_b2 + lane + 32);
        const float b3v = __ldg(dk_b3);
        const float w3a = W3s[lane], w3b = W3s[lane + 32];

        #pragma unroll
        for (int jj = 0; jj < 2; jj++) {
            const int p0 = wp + 16 * jj;
            const int p1r = p0 + 8;
            const bool has1 = p1r < P_;
            const int p1 = has1 ? p1r : p0;
            const int i0 = c_IU[p0], j0 = c_JU[p0];
            const int i1 = c_IU[p1], j1 = c_JU[p1];
            float s0a = 0.f, s0b = 0.f, s1a = 0.f, s1b = 0.f;
            #pragma unroll 4
            for (int k = 0; k < 128; k++) {
                float wk = ww[k];
                float h0 = fmaxf(uu[i0 * 128 + k] + vv[j0 * 128 + k] + wk, 0.f);
                float h1 = fmaxf(uu[i1 * 128 + k] + vv[j1 * 128 + k] + wk, 0.f);
                float w2a = W2s[k * 64 + lane];
                float w2b = W2s[k * 64 + lane + 32];
                s0a = fmaf(h0, w2a, s0a);
                s0b = fmaf(h0, w2b, s0b);
                s1a = fmaf(h1, w2a, s1a);
                s1b = fmaf(h1, w2b, s1b);
            }
            float c0 = fmaxf(s0a + b2a, 0.f) * w3a + fmaxf(s0b + b2b, 0.f) * w3b;
            float c1 = fmaxf(s1a + b2a, 0.f) * w3a + fmaxf(s1b + b2b, 0.f) * w3b;
            #pragma unroll
            for (int off = 16; off; off >>= 1) {
                c0 += __shfl_down_sync(0xffffffffu, c0, off);
                c1 += __shfl_down_sync(0xffffffffu, c1, off);
            }
            if (lane == 0) {
                bool ok0 = read_mask(dvm, b * P_ + p0, mode) && gid[i0] >= 0 && gid[j0] >= 0;
                out_dock[b * P_ + p0] = ok0 ? (c0 + b3v) : NEG;
                if (has1) {
                    bool ok1 = read_mask(dvm, b * P_ + p1, mode) && gid[i1] >= 0 && gid[j1] >= 0;
                    out_dock[b * P_ + p1] = ok1 ? (c1 + b3v) : NEG;
                }
            }
        }
    } else {
        // ---------- MANEUVER + ACTION TYPE ----------
        float* gf8  = (float*)smem_raw;
        float* gl   = (float*)(smem_raw + 4096);
        float* manH = (float*)(smem_raw + 4608);
        float* ath  = (float*)(smem_raw + 8704);
        float* W2m  = (float*)(smem_raw + 8960);
        int*   gid  = (int*)  (smem_raw + 12544);

        if (t < G_) gid[t] = d_group_node[b * G_ + t];
        if (t >= 128) gl[t - 128] = gf[b * 128 + (t - 128)];
        __syncthreads();
        #pragma unroll
        for (int i = 0; i < 4; i++) {
            int idx = t + i * 256;
            int g = idx >> 7, c = idx & 127;
            int n = gid[g];
            gf8[g * 128 + c] = (n >= 0) ? __ldg(nodef + (size_t)n * 128 + c) : 0.f;
        }
        for (int idx = t; idx < 128 * ND_; idx += 256) W2m[idx] = __ldg(mn_W2 + idx);
        __syncthreads();

        if (t < 128) {
            float ma[G_];
            #pragma unroll
            for (int g = 0; g < G_; g++) ma[g] = 0.f;
            float gcm = __ldg(mn_b1 + t);
            float av = (t < 64) ? __ldg(at_b1 + t) : 0.f;
            #pragma unroll 4
            for (int k = 0; k < 128; k++) {
                float wa = __ldg(mn_W1 + k * 128 + t);
                float wb = __ldg(mn_W1 + (128 + k) * 128 + t);
                float gk = gl[k];
                #pragma unroll
                for (int g = 0; g < G_; g++) ma[g] = fmaf(gf8[g * 128 + k], wa, ma[g]);
                gcm = fmaf(gk, wb, gcm);
                if (t < 64) av = fmaf(gk, __ldg(at_W1 + k * 64 + t), av);
            }
            #pragma unroll
            for (int g = 0; g < G_; g++) manH[g * 128 + t] = fmaxf(ma[g] + gcm, 0.f);
            if (t < 64) ath[t] = fmaxf(av, 0.f);
        }
        __syncthreads();

        if (t < G_ * ND_) {
            int g = t / ND_, d = t - g * ND_;
            float s = __ldg(mn_b2 + d);
            #pragma unroll 8
            for (int k = 0; k < 128; k++) s = fmaf(manH[g * 128 + k], W2m[k * ND_ + d], s);
            bool ok = (gid[g] >= 0) && read_mask(mvm, b * G_ * ND_ + t, mode);
            out_man[b * G_ * ND_ + t] = ok ? s : NEG;
        } else if (t >= 64 && t < 64 + AT_) {
            int a = t - 64;
            float s = __ldg(at_b2 + a);
            #pragma unroll 8
            for (int k = 0; k < 64; k++) s = fmaf(ath[k], __ldg(at_W2 + k * AT_ + a), s);
            out_at[b * AT_ + a] = read_mask(atm, b * AT_ + a, mode) ? s : NEG;
        }
    }
}

// ---------------------------------------------------------------------------
extern "C" void kernel_launch(void* const* d_in, const int* in_sizes, int n_in,
                              void* d_out, int out_size) {
    const float* nodef      = (const float*)d_in[0];
    const float* gf         = (const float*)d_in[1];
    const int*   atm        = (const int*)d_in[2];
    const void*  cube_mask  = d_in[3];
    const void*  group_mask = d_in[4];
    /* d_in[5] = batch (unused; segments contiguous) */
    const void*  move_mask  = d_in[6];
    const void*  dvm        = d_in[7];
    const void*  mvm        = d_in[8];
    const float* at_W1 = (const float*)d_in[9];
    const float* at_b1 = (const float*)d_in[10];
    const float* at_W2 = (const float*)d_in[11];
    const float* at_b2 = (const float*)d_in[12];
    const float* cm_W1 = (const float*)d_in[13];
    const float* cm_b1 = (const float*)d_in[14];
    const float* cm_W2 = (const float*)d_in[15];
    const float* cm_b2 = (const float*)d_in[16];
    const float* dk_W1 = (const float*)d_in[17];
    const float* dk_b1 = (const float*)d_in[18];
    const float* dk_W2 = (const float*)d_in[19];
    const float* dk_b2 = (const float*)d_in[20];
    const float* dk_W3 = (const float*)d_in[21];
    const float* dk_b3 = (const float*)d_in[22];
    const float* mn_W1 = (const float*)d_in[23];
    const float* mn_b1 = (const float*)d_in[24];
    const float* mn_W2 = (const float*)d_in[25];
    const float* mn_b2 = (const float*)d_in[26];

    float* out      = (float*)d_out;
    float* out_at   = out;
    float* out_cube = out + (size_t)B_ * AT_;
    float* out_dock = out_cube + (size_t)B_ * MAXC * M_;
    float* out_man  = out_dock + (size_t)B_ * P_;

    cudaFuncSetAttribute(mega_kernel, cudaFuncAttributeMaxDynamicSharedMemorySize, SMEM_DYN);

    setup_kernel<<<B_ + 1, 256>>>(gf, cm_W1, cm_b1, cm_W2, cube_mask, group_mask, atm);
    mega_kernel<<<768, 256, SMEM_DYN>>>(
        nodef, gf, atm, move_mask, dvm, mvm,
        cm_b2,
        at_W1, at_b1, at_W2, at_b2,
        dk_W1, dk_b1, dk_W2, dk_b2, dk_W3, dk_b3,
        mn_W1, mn_b1, mn_W2, mn_b2,
        out_at, out_cube, out_dock, out_man);
}

// round 15
// speedup vs baseline: 1.3109x; 1.0511x over previous
#include <cuda_runtime.h>
#include <cuda_bf16.h>
#include <stdint.h>

#define NEG (-1e9f)
constexpr int B_   = 128;
constexpr int NPG  = 1024;
constexpr int M_   = 24;
constexpr int MAXC = 512;
constexpr int G_   = 8;
constexpr int ND_  = 7;
constexpr int AT_  = 5;
constexpr int P_   = 28;

__device__ int      d_cube_node[B_ * MAXC];
__device__ int      d_group_node[B_ * G_];
__device__ float    d_cm_gc[B_ * 128];
__device__ uint32_t d_W1bf[128 * 68];   // bf16x2 W1^T image (n-major, stride 68 u32)
__device__ uint32_t d_W2bf[24 * 68];    // bf16x2 W2^T image

__constant__ int c_IU[P_] = {0,0,0,0,0,0,0,1,1,1,1,1,1,2,2,2,2,2,3,3,3,3,4,4,4,5,5,6};
__constant__ int c_JU[P_] = {1,2,3,4,5,6,7,2,3,4,5,6,7,3,4,5,6,7,4,5,6,7,5,6,7,6,7,7};

__device__ __forceinline__ int mask_mode(const int* __restrict__ atm) {
    int v = __ldg(atm);
    if (v == 1) return 1;
    if (v == 0x3F800000) return 2;
    return 0;
}
__device__ __forceinline__ bool read_mask(const void* p, long i, int mode) {
    if (mode == 1) return ((const int*)p)[i] != 0;
    if (mode == 2) return ((const float*)p)[i] != 0.f;
    return ((const uint8_t*)p)[i] != 0;
}

// bf16 mma.sync (sm_80+ baseline PTX -> HMMA on sm_103)
__device__ __forceinline__ void mma16816(float* c, uint32_t a0, uint32_t a1,
                                         uint32_t a2, uint32_t a3,
                                         uint32_t b0, uint32_t b1) {
    asm volatile(
        "mma.sync.aligned.m16n8k16.row.col.f32.bf16.bf16.f32 "
        "{%0,%1,%2,%3}, {%4,%5,%6,%7}, {%8,%9}, {%0,%1,%2,%3};"
        : "+f"(c[0]), "+f"(c[1]), "+f"(c[2]), "+f"(c[3])
        : "r"(a0), "r"(a1), "r"(a2), "r"(a3), "r"(b0), "r"(b1));
}
__device__ __forceinline__ uint32_t bf2(float x, float y) {
    __nv_bfloat162 p = __float22bfloat162_rn(make_float2(x, y));
    return *(uint32_t*)&p;
}

// ---------------------------------------------------------------------------
// setup: blocks 0..127 per-batch work; block 128 converts cube weights to bf16
// ---------------------------------------------------------------------------
__global__ __launch_bounds__(256) void setup_kernel(
    const float* __restrict__ gf,
    const float* __restrict__ cmW1, const float* __restrict__ cmb1,
    const float* __restrict__ cmW2,
    const void* __restrict__ cube_mask, const void* __restrict__ group_mask,
    const int* __restrict__ atm)
{
    const int t = threadIdx.x;
    if (blockIdx.x == B_) {
        const int n = t & 127, kh = (t >> 7) * 32;
        const float* wp = cmW1 + n;
        #pragma unroll 8
        for (int kk = 0; kk < 32; kk++) {
            int k2 = kh + kk;
            float w0 = __ldg(wp + (2 * k2) * 128);
            float w1 = __ldg(wp + (2 * k2 + 1) * 128);
            d_W1bf[n * 68 + k2] = bf2(w0, w1);
        }
        for (int idx = t; idx < 24 * 64; idx += 256) {
            int nn = idx % 24, kk = idx / 24;
            float w0 = __ldg(cmW2 + (2 * kk) * 24 + nn);
            float w1 = __ldg(cmW2 + (2 * kk + 1) * 24 + nn);
            d_W2bf[nn * 68 + kk] = bf2(w0, w1);
        }
        return;
    }

    const int b = blockIdx.x;
    const int w = t >> 5, lane = t & 31;
    const int mode = mask_mode(atm);
    __shared__ float g[128];
    __shared__ float sred[4][128];
    __shared__ int wtc[4], wtg[4], stc, stg;

    if (t < 128) g[t] = gf[b * 128 + t];
    __syncthreads();

    unsigned cm8 = 0, gm8 = 0;
    int cex = 0, gex = 0;

    if (w < 4) {
        const float4* W4 = (const float4*)cmW1;
        float4 a = make_float4(0.f, 0.f, 0.f, 0.f);
        #pragma unroll
        for (int kk = 0; kk < 32; kk++) {
            int k = 32 * w + kk;
            float4 wv = __ldg(&W4[(128 + k) * 32 + lane]);
            float gk = g[k];
            a.x = fmaf(gk, wv.x, a.x);
            a.y = fmaf(gk, wv.y, a.y);
            a.z = fmaf(gk, wv.z, a.z);
            a.w = fmaf(gk, wv.w, a.w);
        }
        *(float4*)&sred[w][4 * lane] = a;
    } else if (mode == 1) {
        const int w4 = w - 4;
        const int4* cm4 = (const int4*)cube_mask + b * 256 + w4 * 64 + lane * 2;
        const int4* gm4 = (const int4*)group_mask + b * 256 + w4 * 64 + lane * 2;
        int4 c0 = __ldg(cm4), c1 = __ldg(cm4 + 1);
        int4 g0 = __ldg(gm4), g1 = __ldg(gm4 + 1);
        cm8 = (c0.x != 0) | ((c0.y != 0) << 1) | ((c0.z != 0) << 2) | ((c0.w != 0) << 3)
            | ((c1.x != 0) << 4) | ((c1.y != 0) << 5) | ((c1.z != 0) << 6) | ((c1.w != 0) << 7);
        gm8 = (g0.x != 0) | ((g0.y != 0) << 1) | ((g0.z != 0) << 2) | ((g0.w != 0) << 3)
            | ((g1.x != 0) << 4) | ((g1.y != 0) << 5) | ((g1.z != 0) << 6) | ((g1.w != 0) << 7);
        int cs = __popc(cm8), gs = __popc(gm8);
        int csi = cs, gsi = gs;
        #pragma unroll
        for (int off = 1; off < 32; off <<= 1) {
            int v1 = __shfl_up_sync(0xffffffffu, csi, off);
            int v2 = __shfl_up_sync(0xffffffffu, gsi, off);
            if (lane >= off) { csi += v1; gsi += v2; }
        }
        cex = csi - cs; gex = gsi - gs;
        if (lane == 31) { wtc[w4] = csi; wtg[w4] = gsi; }
    } else if (w == 4) {
        int cc = 0, gc = 0;
        for (int c = 0; c < NPG; c += 32) {
            long node = (long)b * NPG + c + lane;
            bool cm = read_mask(cube_mask, node, mode);
            bool gm = read_mask(group_mask, node, mode);
            unsigned cb = __ballot_sync(0xffffffffu, cm);
            unsigned gb = __ballot_sync(0xffffffffu, gm);
            unsigned lt = (1u << lane) - 1u;
            if (cm) { int p = cc + __popc(cb & lt); if (p < MAXC) d_cube_node[b * MAXC + p] = (int)node; }
            if (gm) { int p = gc + __popc(gb & lt); if (p < G_)   d_group_node[b * G_ + p] = (int)node; }
            cc += __popc(cb);
            gc += __popc(gb);
        }
        if (lane == 0) { stc = cc; stg = gc; }
    }
    __syncthreads();

    if (t < 128)
        d_cm_gc[b * 128 + t] = __ldg(cmb1 + t) +
            ((sred[0][t] + sred[1][t]) + (sred[2][t] + sred[3][t]));

    int tc, tg;
    if (mode == 1) {
        tc = wtc[0] + wtc[1] + wtc[2] + wtc[3];
        tg = wtg[0] + wtg[1] + wtg[2] + wtg[3];
        if (w >= 4) {
            const int w4 = w - 4;
            int cbase = 0, gbase = 0;
            #pragma unroll
            for (int i = 0; i < 4; i++) if (i < w4) { cbase += wtc[i]; gbase += wtg[i]; }
            const int nb = b * NPG + w4 * 256 + lane * 8;
            #pragma unroll
            for (int j = 0; j < 8; j++) {
                if ((cm8 >> j) & 1) {
                    int p = cbase + cex + __popc(cm8 & ((1u << j) - 1u));
                    if (p < MAXC) d_cube_node[b * MAXC + p] = nb + j;
                }
                if ((gm8 >> j) & 1) {
                    int p = gbase + gex + __popc(gm8 & ((1u << j) - 1u));
                    if (p < G_) d_group_node[b * G_ + p] = nb + j;
                }
            }
        }
    } else {
        tc = stc; tg = stg;
    }
    for (int p = tc + t; p < MAXC; p += 256) d_cube_node[b * MAXC + p] = -1;
    for (int p = tg + t; p < G_; p += 256)   d_group_node[b * G_ + p] = -1;
}

// ---------------------------------------------------------------------------
// mega kernel, 256 threads/block, 3 blocks/SM:
//   blocks 0-127 docking, 128-255 man+AT (long-latency heads FIRST),
//   blocks 256-767 cube (mma.sync bf16, register-resident H)
// cube dyn smem: Xs 0..34816 | Ws1 ..69632 | Ws2 ..76160 | nodes ..76672
// ---------------------------------------------------------------------------
constexpr int SMEM_DYN = 76672;

__global__ __launch_bounds__(256, 3) void mega_kernel(
    const float* __restrict__ nodef, const float* __restrict__ gf,
    const int* __restrict__ atm, const void* __restrict__ move_mask,
    const void* __restrict__ dvm, const void* __restrict__ mvm,
    const float* __restrict__ cm_b2,
    const float* __restrict__ at_W1, const float* __restrict__ at_b1,
    const float* __restrict__ at_W2, const float* __restrict__ at_b2,
    const float* __restrict__ dk_W1, const float* __restrict__ dk_b1,
    const float* __restrict__ dk_W2, const float* __restrict__ dk_b2,
    const float* __restrict__ dk_W3, const float* __restrict__ dk_b3,
    const float* __restrict__ mn_W1, const float* __restrict__ mn_b1,
    const float* __restrict__ mn_W2, const float* __restrict__ mn_b2,
    float* __restrict__ out_at, float* __restrict__ out_cube,
    float* __restrict__ out_dock, float* __restrict__ out_man)
{
    extern __shared__ __align__(16) char smem_raw[];
    const int t = threadIdx.x;
    const int mode = mask_mode(atm);

    if (blockIdx.x >= 256) {
        // ===================== CUBE =====================
        uint32_t* Xs  = (uint32_t*)smem_raw;                 // [128][68] bf16x2
        uint32_t* Ws1 = (uint32_t*)(smem_raw + 34816);
        uint32_t* Ws2 = (uint32_t*)(smem_raw + 69632);
        int*   nodes = (int*)(smem_raw + 76160);

        const int row0 = (blockIdx.x - 256) * 128;
        const int b = row0 >> 9;
        const int w = t >> 5, lane = t & 31;
        const int gid4 = lane >> 2, tig = lane & 3;

        // W images: coalesced uint4 copies from precomputed globals (L2-hot)
        {
            const uint4* src1 = (const uint4*)d_W1bf;
            uint4* dst1 = (uint4*)Ws1;
            #pragma unroll
            for (int i = 0; i < 8; i++) dst1[t + i * 256] = src1[t + i * 256];
            if (t < 128) dst1[t + 2048] = src1[t + 2048];
            const uint4* src2 = (const uint4*)d_W2bf;
            uint4* dst2 = (uint4*)Ws2;
            if (t < 204) { dst2[t] = src2[t]; dst2[t + 204] = src2[t + 204]; }
        }
        if (t < 128) nodes[t] = d_cube_node[row0 + t];
        // X: warp-per-row, lane <-> float4 of row (coalesced)
        #pragma unroll
        for (int i = 0; i < 16; i++) {
            int r = 16 * w + i;
            int nd = __ldg(&d_cube_node[row0 + r]);
            uint64_t v = 0ull;
            if (nd >= 0) {
                float4 x = __ldg((const float4*)(nodef + (size_t)nd * 128) + lane);
                v = ((uint64_t)bf2(x.z, x.w) << 32) | (uint64_t)bf2(x.x, x.y);
            }
            *(uint64_t*)&Xs[r * 68 + 2 * lane] = v;
        }
        __syncthreads();

        const int ar0 = 16 * w + gid4;
        const uint32_t* Xr0 = Xs + ar0 * 68 + tig;
        const uint32_t* Xr1 = Xs + (ar0 + 8) * 68 + tig;
        const float* gcp = d_cm_gc + b * 128;

        float acc[8][4];
        uint32_t h0[16], h1[16];

        // ---- GEMM1 pass 0: out cols 0..63 -> h0 (registers) ----
        #pragma unroll
        for (int i = 0; i < 8; i++)
            #pragma unroll
            for (int j = 0; j < 4; j++) acc[i][j] = 0.f;
        #pragma unroll
        for (int ks = 0; ks < 8; ks++) {
            uint32_t a0 = Xr0[8 * ks],     a1 = Xr1[8 * ks];
            uint32_t a2 = Xr0[8 * ks + 4], a3 = Xr1[8 * ks + 4];
            #pragma unroll
            for (int nt = 0; nt < 8; nt++) {
                const uint32_t* bp = Ws1 + (8 * nt + gid4) * 68 + 8 * ks + tig;
                mma16816(acc[nt], a0, a1, a2, a3, bp[0], bp[4]);
            }
        }
        #pragma unroll
        for (int nt = 0; nt < 8; nt++) {
            int c0 = 8 * nt + 2 * tig;
            float g0 = __ldg(gcp + c0), g1 = __ldg(gcp + c0 + 1);
            h0[nt]     = bf2(fmaxf(acc[nt][0] + g0, 0.f), fmaxf(acc[nt][1] + g1, 0.f));
            h0[nt + 8] = bf2(fmaxf(acc[nt][2] + g0, 0.f), fmaxf(acc[nt][3] + g1, 0.f));
        }

        // ---- GEMM1 pass 1: out cols 64..127 -> h1 (registers) ----
        #pragma unroll
        for (int i = 0; i < 8; i++)
            #pragma unroll
            for (int j = 0; j < 4; j++) acc[i][j] = 0.f;
        #pragma unroll
        for (int ks = 0; ks < 8; ks++) {
            uint32_t a0 = Xr0[8 * ks],     a1 = Xr1[8 * ks];
            uint32_t a2 = Xr0[8 * ks + 4], a3 = Xr1[8 * ks + 4];
            #pragma unroll
            for (int nt = 0; nt < 8; nt++) {
                const uint32_t* bp = Ws1 + (64 + 8 * nt + gid4) * 68 + 8 * ks + tig;
                mma16816(acc[nt], a0, a1, a2, a3, bp[0], bp[4]);
            }
        }
        #pragma unroll
        for (int nt = 0; nt < 8; nt++) {
            int c1 = 64 + 8 * nt + 2 * tig;
            float g0 = __ldg(gcp + c1), g1 = __ldg(gcp + c1 + 1);
            h1[nt]     = bf2(fmaxf(acc[nt][0] + g0, 0.f), fmaxf(acc[nt][1] + g1, 0.f));
            h1[nt + 8] = bf2(fmaxf(acc[nt][2] + g0, 0.f), fmaxf(acc[nt][3] + g1, 0.f));
        }

        // GEMM2: H @ W2^T (N=24), A-fragments taken directly from h0/h1.
        // k-step ks: a0/a1 = GEMM1 n-tile 2ks (rows ar0/ar0+8), a2/a3 = tile 2ks+1.
        float acc2[3][4];
        #pragma unroll
        for (int i = 0; i < 3; i++)
            #pragma unroll
            for (int j = 0; j < 4; j++) acc2[i][j] = 0.f;
        #pragma unroll
        for (int ks = 0; ks < 8; ks++) {
            uint32_t a0, a1, a2, a3;
            if (ks < 4) {
                a0 = h0[2 * ks];     a1 = h0[2 * ks + 8];
                a2 = h0[2 * ks + 1]; a3 = h0[2 * ks + 9];
            } else {
                int q = ks - 4;
                a0 = h1[2 * q];      a1 = h1[2 * q + 8];
                a2 = h1[2 * q + 1];  a3 = h1[2 * q + 9];
            }
            #pragma unroll
            for (int nt = 0; nt < 3; nt++) {
                const uint32_t* bp = Ws2 + (8 * nt + gid4) * 68 + 8 * ks + tig;
                mma16816(acc2[nt], a0, a1, a2, a3, bp[0], bp[4]);
            }
        }
        __syncwarp();   // warp's Xs reads (GEMM1) done before overwrite as D-stage

        // stage D2+bias into warp-own region of Xs (384 floats)
        float* Dw = (float*)(Xs + (16 * w) * 68);
        #pragma unroll
        for (int nt = 0; nt < 3; nt++) {
            int c0 = 8 * nt + 2 * tig;
            float bb0 = __ldg(cm_b2 + c0), bb1 = __ldg(cm_b2 + c0 + 1);
            Dw[gid4 * 24 + c0]           = acc2[nt][0] + bb0;
            Dw[gid4 * 24 + c0 + 1]       = acc2[nt][1] + bb1;
            Dw[(gid4 + 8) * 24 + c0]     = acc2[nt][2] + bb0;
            Dw[(gid4 + 8) * 24 + c0 + 1] = acc2[nt][3] + bb1;
        }
        __syncwarp();

        // warp-local masked vector write: 96 float4
        const long e0 = (long)(row0 + 16 * w) * 24;
        #pragma unroll
        for (int j = 0; j < 3; j++) {
            int idx4 = j * 32 + lane;
            float4 v = ((const float4*)Dw)[idx4];
            float r4[4] = {v.x, v.y, v.z, v.w};
            float o4[4];
            if (mode == 1) {
                int4 mk = __ldg((const int4*)move_mask + (e0 >> 2) + idx4);
                int m4[4] = {mk.x, mk.y, mk.z, mk.w};
                #pragma unroll
                for (int q = 0; q < 4; q++) {
                    int e = idx4 * 4 + q;
                    bool ok = (nodes[16 * w + e / 24] >= 0) && (m4[q] != 0);
                    o4[q] = ok ? r4[q] : NEG;
                }
            } else {
                #pragma unroll
                for (int q = 0; q < 4; q++) {
                    int e = idx4 * 4 + q;
                    bool ok = (nodes[16 * w + e / 24] >= 0) && read_mask(move_mask, e0 + e, mode);
                    o4[q] = ok ? r4[q] : NEG;
                }
            }
            *(float4*)(out_cube + e0 + idx4 * 4) = make_float4(o4[0], o4[1], o4[2], o4[3]);
        }
        return;
    }

    // ===================== HEADS (scheduled first) =====================
    const int b = blockIdx.x & 127;
    if (blockIdx.x < 128) {
        // ---------- DOCKING ----------
        float* gf8 = (float*)smem_raw;
        float* gl  = (float*)(smem_raw + 4096);
        float* uu  = (float*)(smem_raw + 4608);
        float* vv  = (float*)(smem_raw + 8704);
        float* ww  = (float*)(smem_raw + 12800);
        float* W3s = (float*)(smem_raw + 13312);
        int*   gid = (int*)  (smem_raw + 13568);
        float* W2s = (float*)(smem_raw + 13600);

        if (t < G_) gid[t] = d_group_node[b * G_ + t];
        if (t >= 128) gl[t - 128] = gf[b * 128 + (t - 128)];
        __syncthreads();
        #pragma unroll
        for (int i = 0; i < 4; i++) {
            int idx = t + i * 256;
            int g = idx >> 7, c = idx & 127;
            int n = gid[g];
            gf8[g * 128 + c] = (n >= 0) ? __ldg(nodef + (size_t)n * 128 + c) : 0.f;
        }
        #pragma unroll
        for (int i = 0; i < 32; i++) W2s[t + i * 256] = __ldg(dk_W2 + t + i * 256);
        if (t < 64) W3s[t] = __ldg(dk_W3 + t);
        __syncthreads();

        // hidden pass split over all 256 threads: t<128 -> u ; t>=128 -> v + w
        {
            const int half = t >> 7, tt = t & 127;
            float ua[G_];
            #pragma unroll
            for (int g = 0; g < G_; g++) ua[g] = 0.f;
            float wv = half ? __ldg(dk_b1 + tt) : 0.f;
            const float* Wbase = dk_W1 + (half ? 128 * 128 : 0) + tt;
            const float* Wc = dk_W1 + 256 * 128 + tt;
            #pragma unroll 4
            for (int k = 0; k < 128; k++) {
                float wa = __ldg(Wbase + k * 128);
                #pragma unroll
                for (int g = 0; g < G_; g++) ua[g] = fmaf(gf8[g * 128 + k], wa, ua[g]);
                if (half) wv = fmaf(gl[k], __ldg(Wc + k * 128), wv);
            }
            if (half == 0) {
                #pragma unroll
                for (int g = 0; g < G_; g++) uu[g * 128 + tt] = ua[g];
            } else {
                #pragma unroll
                for (int g = 0; g < G_; g++) vv[g * 128 + tt] = ua[g];
                ww[tt] = wv;
            }
        }
        __syncthreads();

        const int wp = t >> 5, lane = t & 31;
        const float b2a = __ldg(dk_b2 + lane);
        const float b2b = __ldg(dk_b2 + lane + 32);
        const float b3v = __ldg(dk_b3);
        const float w3a = W3s[lane], w3b = W3s[lane + 32];

        #pragma unroll
        for (int jj = 0; jj < 2; jj++) {
            const int p0 = wp + 16 * jj;
            const int p1r = p0 + 8;
            const bool has1 = p1r < P_;
            const int p1 = has1 ? p1r : p0;
            const int i0 = c_IU[p0], j0 = c_JU[p0];
            const int i1 = c_IU[p1], j1 = c_JU[p1];
            float s0a = 0.f, s0b = 0.f, s1a = 0.f, s1b = 0.f;
            #pragma unroll 4
            for (int k = 0; k < 128; k++) {
                float wk = ww[k];
                float h0v = fmaxf(uu[i0 * 128 + k] + vv[j0 * 128 + k] + wk, 0.f);
                float h1v = fmaxf(uu[i1 * 128 + k] + vv[j1 * 128 + k] + wk, 0.f);
                float w2a = W2s[k * 64 + lane];
                float w2b = W2s[k * 64 + lane + 32];
                s0a = fmaf(h0v, w2a, s0a);
                s0b = fmaf(h0v, w2b, s0b);
                s1a = fmaf(h1v, w2a, s1a);
                s1b = fmaf(h1v, w2b, s1b);
            }
            float c0 = fmaxf(s0a + b2a, 0.f) * w3a + fmaxf(s0b + b2b, 0.f) * w3b;
            float c1 = fmaxf(s1a + b2a, 0.f) * w3a + fmaxf(s1b + b2b, 0.f) * w3b;
            #pragma unroll
            for (int off = 16; off; off >>= 1) {
                c0 += __shfl_down_sync(0xffffffffu, c0, off);
                c1 += __shfl_down_sync(0xffffffffu, c1, off);
            }
            if (lane == 0) {
                bool ok0 = read_mask(dvm, b * P_ + p0, mode) && gid[i0] >= 0 && gid[j0] >= 0;
                out_dock[b * P_ + p0] = ok0 ? (c0 + b3v) : NEG;
                if (has1) {
                    bool ok1 = read_mask(dvm, b * P_ + p1, mode) && gid[i1] >= 0 && gid[j1] >= 0;
                    out_dock[b * P_ + p1] = ok1 ? (c1 + b3v) : NEG;
                }
            }
        }
    } else {
        // ---------- MANEUVER + ACTION TYPE ----------
        float* gf8  = (float*)smem_raw;
        float* gl   = (float*)(smem_raw + 4096);
        float* manH = (float*)(smem_raw + 4608);
        float* ath  = (float*)(smem_raw + 8704);
        float* W2m  = (float*)(smem_raw + 8960);
        int*   gid  = (int*)  (smem_raw + 12544);

        if (t < G_) gid[t] = d_group_node[b * G_ + t];
        if (t >= 128) gl[t - 128] = gf[b * 128 + (t - 128)];
        __syncthreads();
        #pragma unroll
        for (int i = 0; i < 4; i++) {
            int idx = t + i * 256;
            int g = idx >> 7, c = idx & 127;
            int n = gid[g];
            gf8[g * 128 + c] = (n >= 0) ? __ldg(nodef + (size_t)n * 128 + c) : 0.f;
        }
        for (int idx = t; idx < 128 * ND_; idx += 256) W2m[idx] = __ldg(mn_W2 + idx);
        __syncthreads();

        if (t < 128) {
            float ma[G_];
            #pragma unroll
            for (int g = 0; g < G_; g++) ma[g] = 0.f;
            float gcm = __ldg(mn_b1 + t);
            float av = (t < 64) ? __ldg(at_b1 + t) : 0.f;
            #pragma unroll 4
            for (int k = 0; k < 128; k++) {
                float wa = __ldg(mn_W1 + k * 128 + t);
                float wb = __ldg(mn_W1 + (128 + k) * 128 + t);
                float gk = gl[k];
                #pragma unroll
                for (int g = 0; g < G_; g++) ma[g] = fmaf(gf8[g * 128 + k], wa, ma[g]);
                gcm = fmaf(gk, wb, gcm);
                if (t < 64) av = fmaf(gk, __ldg(at_W1 + k * 64 + t), av);
            }
            #pragma unroll
            for (int g = 0; g < G_; g++) manH[g * 128 + t] = fmaxf(ma[g] + gcm, 0.f);
            if (t < 64) ath[t] = fmaxf(av, 0.f);
        }
        __syncthreads();

        if (t < G_ * ND_) {
            int g = t / ND_, d = t - g * ND_;
            float s = __ldg(mn_b2 + d);
            #pragma unroll 8
            for (int k = 0; k < 128; k++) s = fmaf(manH[g * 128 + k], W2m[k * ND_ + d], s);
            bool ok = (gid[g] >= 0) && read_mask(mvm, b * G_ * ND_ + t, mode);
            out_man[b * G_ * ND_ + t] = ok ? s : NEG;
        } else if (t >= 64 && t < 64 + AT_) {
            int a = t - 64;
            float s = __ldg(at_b2 + a);
            #pragma unroll 8
            for (int k = 0; k < 64; k++) s = fmaf(ath[k], __ldg(at_W2 + k * AT_ + a), s);
            out_at[b * AT_ + a] = read_mask(atm, b * AT_ + a, mode) ? s : NEG;
        }
    }
}

// ---------------------------------------------------------------------------
extern "C" void kernel_launch(void* const* d_in, const int* in_sizes, int n_in,
                              void* d_out, int out_size) {
    const float* nodef      = (const float*)d_in[0];
    const float* gf         = (const float*)d_in[1];
    const int*   atm        = (const int*)d_in[2];
    const void*  cube_mask  = d_in[3];
    const void*  group_mask = d_in[4];
    /* d_in[5] = batch (unused; segments contiguous) */
    const void*  move_mask  = d_in[6];
    const void*  dvm        = d_in[7];
    const void*  mvm        = d_in[8];
    const float* at_W1 = (const float*)d_in[9];
    const float* at_b1 = (const float*)d_in[10];
    const float* at_W2 = (const float*)d_in[11];
    const float* at_b2 = (const float*)d_in[12];
    const float* cm_W1 = (const float*)d_in[13];
    const float* cm_b1 = (const float*)d_in[14];
    const float* cm_W2 = (const float*)d_in[15];
    const float* cm_b2 = (const float*)d_in[16];
    const float* dk_W1 = (const float*)d_in[17];
    const float* dk_b1 = (const float*)d_in[18];
    const float* dk_W2 = (const float*)d_in[19];
    const float* dk_b2 = (const float*)d_in[20];
    const float* dk_W3 = (const float*)d_in[21];
    const float* dk_b3 = (const float*)d_in[22];
    const float* mn_W1 = (const float*)d_in[23];
    const float* mn_b1 = (const float*)d_in[24];
    const float* mn_W2 = (const float*)d_in[25];
    const float* mn_b2 = (const float*)d_in[26];

    float* out      = (float*)d_out;
    float* out_at   = out;
    float* out_cube = out + (size_t)B_ * AT_;
    float* out_dock = out_cube + (size_t)B_ * MAXC * M_;
    float* out_man  = out_dock + (size_t)B_ * P_;

    cudaFuncSetAttribute(mega_kernel, cudaFuncAttributeMaxDynamicSharedMemorySize, SMEM_DYN);

    setup_kernel<<<B_ + 1, 256>>>(gf, cm_W1, cm_b1, cm_W2, cube_mask, group_mask, atm);
    mega_kernel<<<768, 256, SMEM_DYN>>>(
        nodef, gf, atm, move_mask, dvm, mvm,
        cm_b2,
        at_W1, at_b1, at_W2, at_b2,
        dk_W1, dk_b1, dk_W2, dk_b2, dk_W3, dk_b3,
        mn_W1, mn_b1, mn_W2, mn_b2,
        out_at, out_cube, out_dock, out_man);
}